// round 2
// baseline (speedup 1.0000x reference)
#include <cuda_runtime.h>
#include <math.h>

// Sizes: B=2, Cin=32, G=V=M=4, H=W=28, P=7, MID=48, HEADS=4, POS=16, Cout=64
// q/k/v layout: [(b*4+h)*4+g][yx][48c]   (1204224 floats each)
// g_pe: [v*49+kl][32c] (row 0..15, col 16..31)
// g_ge: [(v*4+g)*4+m][16c]
// g_o : [(b*4+v)*784+yx][192i]  with i = c*4+h

__device__ float g_q[1204224];
__device__ float g_k[1204224];
__device__ float g_v[1204224];
__device__ float g_pe[6272];
__device__ float g_ge[1024];
__device__ float g_o[1204224];

// ---------------------------------------------------------------------------
// PE MLP: h = t*w1+b1 ; LayerNorm(16) ; swish ; e = h@w2^T + b2
// ---------------------------------------------------------------------------
__device__ __forceinline__ void pe_mlp(float tval,
    const float* __restrict__ w1, const float* __restrict__ b1,
    const float* __restrict__ lng, const float* __restrict__ lnb,
    const float* __restrict__ w2, const float* __restrict__ b2,
    float* outp)
{
    float hv[16];
    float mu = 0.f;
#pragma unroll
    for (int j = 0; j < 16; ++j) { hv[j] = tval * w1[j] + b1[j]; mu += hv[j]; }
    mu *= (1.f / 16.f);
    float var = 0.f;
#pragma unroll
    for (int j = 0; j < 16; ++j) { float d = hv[j] - mu; var += d * d; }
    var *= (1.f / 16.f);
    float rstd = rsqrtf(var + 1e-5f);
#pragma unroll
    for (int j = 0; j < 16; ++j) {
        float t = (hv[j] - mu) * rstd * lng[j] + lnb[j];
        hv[j] = t / (1.f + expf(-t));
    }
#pragma unroll
    for (int j = 0; j < 16; ++j) {
        float e = b2[j];
#pragma unroll
        for (int t = 0; t < 16; ++t) e += hv[t] * w2[j * 16 + t];
        outp[j] = e;
    }
}

__global__ void pe_kernel(
    const float* __restrict__ rw1, const float* __restrict__ rb1,
    const float* __restrict__ rlg, const float* __restrict__ rlb,
    const float* __restrict__ rw2, const float* __restrict__ rb2,
    const float* __restrict__ cw1, const float* __restrict__ cb1,
    const float* __restrict__ clg, const float* __restrict__ clb,
    const float* __restrict__ cw2, const float* __restrict__ cb2,
    const float* __restrict__ ridx, const float* __restrict__ cidx,
    const float* __restrict__ gemb, const int* __restrict__ gidx)
{
    int tid = threadIdx.x;
    if (tid < 196) {
        float er[16], ec[16];
        pe_mlp(ridx[tid], rw1, rb1, rlg, rlb, rw2, rb2, er);
        pe_mlp(cidx[tid], cw1, cb1, clg, clb, cw2, cb2, ec);
#pragma unroll
        for (int j = 0; j < 16; ++j) {
            g_pe[tid * 32 + j]      = er[j];
            g_pe[tid * 32 + 16 + j] = ec[j];
        }
    }
    for (int e = tid; e < 1024; e += blockDim.x) {
        int vgm = e >> 4, c = e & 15;
        g_ge[e] = gemb[gidx[vgm] * 16 + c];
    }
}

// ---------------------------------------------------------------------------
// proj: C[576 x 6272] = [Wq;Wk;Wv][576x32] * X[32x6272], scatter to g_q/k/v
// ---------------------------------------------------------------------------
__global__ void __launch_bounds__(256) proj_kernel(
    const float* __restrict__ x,
    const float* __restrict__ Wq, const float* __restrict__ bq,
    const float* __restrict__ Wk, const float* __restrict__ bk,
    const float* __restrict__ Wv, const float* __restrict__ bv)
{
    __shared__ float As[32 * 68];
    __shared__ float Bs[32 * 68];
    int tid = threadIdx.x;
    int n0 = blockIdx.x * 64;
    int r0 = blockIdx.y * 64;

#pragma unroll
    for (int k = 0; k < 8; ++k) {
        int i = tid + k * 256;
        int ci = i & 31, row = i >> 5;
        int rg = r0 + row;
        int which = rg / 192, r = rg - which * 192;
        const float* Wm = (which == 0) ? Wq : (which == 1 ? Wk : Wv);
        As[ci * 68 + row] = Wm[r * 32 + ci];
    }
#pragma unroll
    for (int k = 0; k < 8; ++k) {
        int i = tid + k * 256;
        int nl = i & 63, ci = i >> 6;
        int n = n0 + nl;
        int bb = n / 3136, rem = n - bb * 3136;
        Bs[ci * 68 + nl] = x[bb * 100352 + ci * 3136 + rem];
    }
    __syncthreads();

    int tx = tid & 15, ty = tid >> 4;
    float acc[4][4] = {};
#pragma unroll
    for (int ci = 0; ci < 32; ++ci) {
        float4 a4 = *(const float4*)&As[ci * 68 + ty * 4];
        float4 b4 = *(const float4*)&Bs[ci * 68 + tx * 4];
        float av[4] = { a4.x, a4.y, a4.z, a4.w };
        float bw[4] = { b4.x, b4.y, b4.z, b4.w };
#pragma unroll
        for (int u = 0; u < 4; ++u)
#pragma unroll
            for (int w = 0; w < 4; ++w) acc[u][w] += av[u] * bw[w];
    }

#pragma unroll
    for (int u = 0; u < 4; ++u) {
        int rg = r0 + ty * 4 + u;
        int which = rg / 192, r = rg - which * 192;
        int c = r >> 2, hh = r & 3;
        float bias = ((which == 0) ? bq : (which == 1 ? bk : bv))[r];
        float* dst = (which == 0) ? g_q : (which == 1 ? g_k : g_v);
#pragma unroll
        for (int w = 0; w < 4; ++w) {
            int n = n0 + tx * 4 + w;
            int bb = n / 3136, rem = n - bb * 3136;
            int gg = rem / 784, yx = rem - gg * 784;
            dst[(((bb * 4 + hh) * 4 + gg) * 784 + yx) * 48 + c] = acc[u][w] + bias;
        }
    }
}

// ---------------------------------------------------------------------------
// attn: one block per (b,h, 4x4 pixel tile). 256 threads = 8 warps, 2 sites/warp.
// ---------------------------------------------------------------------------
#define SM_PE    0        // [196][33]
#define SM_GE    6468     // [64][16]
#define SM_QS    7492     // [16 sites][4 g][48 c]
#define SM_SLAB  10564    // [48 c][401]  pos = m*100 + sy*10 + sx  (sy,sx in 0..9)
#define SM_SCR   29812    // per-warp: rc 784 | w0 784 | w1 784 | gs 64 = 2416
#define SCR_WARP 2416
#define ATTN_SMEM_FLOATS (SM_SCR + 8 * SCR_WARP)   // 49140
#define ATTN_SMEM_BYTES  (ATTN_SMEM_FLOATS * 4)    // 196560

__global__ void __launch_bounds__(256, 1) attn_kernel()
{
    extern __shared__ float sm[];
    float* pes  = sm + SM_PE;
    float* ges  = sm + SM_GE;
    float* qs   = sm + SM_QS;
    float* slab = sm + SM_SLAB;

    const int tid  = threadIdx.x, lane = tid & 31, warp = tid >> 5;
    const int tile = blockIdx.x % 49;
    const int bh   = blockIdx.x / 49;
    const int b    = bh >> 2, h = bh & 3;
    const int ty0  = (tile / 7) * 4, tx0 = (tile % 7) * 4;

    for (int i = tid; i < 6272; i += 256) pes[(i >> 5) * 33 + (i & 31)] = g_pe[i];
    for (int i = tid; i < 1024; i += 256) ges[i] = g_ge[i];
    for (int i = tid; i < 3072; i += 256) {
        int site = i / 192, r = i - site * 192, gg = r / 48, c = r - gg * 48;
        int yx = (ty0 + (site >> 2)) * 28 + tx0 + (site & 3);
        qs[i] = g_q[((bh * 4 + gg) * 784 + yx) * 48 + c];
    }
    for (int i = tid; i < 19200; i += 256) {
        int c = i % 48, r = i / 48;
        int sx = r % 10, t2 = r / 10, sy = t2 % 10, m = t2 / 10;
        int y = ty0 - 3 + sy, xx = tx0 - 3 + sx;
        float val = 0.f;
        if ((unsigned)y < 28u && (unsigned)xx < 28u)
            val = g_k[((bh * 4 + m) * 784 + y * 28 + xx) * 48 + c];
        slab[c * 401 + m * 100 + sy * 10 + sx] = val;
    }
    __syncthreads();

    float* scr  = sm + SM_SCR + warp * SCR_WARP;
    float* rc_s = scr;          // 784: [v][g][49 kl]
    float* gs_s = scr + 2352;   // 64 : [v][g][4 m]

    // =============== Phase 1: scores + softmax -> w[p][4v] =================
    for (int si = 0; si < 2; ++si) {
        const int site = warp * 2 + si;
        const int ly = site >> 2, lx = site & 3;
        const float* qsi = qs + site * 192;
        float* w_s = scr + 784 + si * 784;     // [196 p][4 v]

        // group scores gs[v][g][m] (64 values, 2 per lane)
#pragma unroll
        for (int u = 0; u < 2; ++u) {
            int e = lane * 2 + u;
            int gg = (e >> 2) & 3;
            float a = 0.f;
#pragma unroll
            for (int c = 0; c < 16; ++c)
                a += qsi[gg * 48 + 32 + c] * ges[e * 16 + c];
            gs_s[e] = a;
        }

        // per-lane entry mapping: p = lane + 32*t over 196 = 4m x 49kl
        int kl_t[7], m_t[7], pos_t[7];
        bool valid[7], act[7];
#pragma unroll
        for (int t = 0; t < 7; ++t) {
            int p = lane + 32 * t;
            act[t] = (p < 196);
            int pc = act[t] ? p : 0;
            int m = pc / 49, kl = pc - m * 49, kk = kl / 7, ll = kl - kk * 7;
            kl_t[t] = kl; m_t[t] = m;
            pos_t[t] = m * 100 + (ly + kk) * 10 + (lx + ll);
            int y = ty0 + ly + kk - 3, xx = tx0 + lx + ll - 3;
            valid[t] = act[t] && ((unsigned)y < 28u) && ((unsigned)xx < 28u);
        }

        // content[g][t] = sum_c q[g][c] * k_slab[c][pos_t]
        float acc[4][7];
#pragma unroll
        for (int gg = 0; gg < 4; ++gg)
#pragma unroll
            for (int t = 0; t < 7; ++t) acc[gg][t] = 0.f;
        for (int c = 0; c < 48; ++c) {
            float q0 = qsi[c], q1 = qsi[48 + c], q2 = qsi[96 + c], q3 = qsi[144 + c];
            const float* sr = slab + c * 401;
#pragma unroll
            for (int t = 0; t < 7; ++t) {
                float sv = sr[pos_t[t]];
                acc[0][t] += q0 * sv; acc[1][t] += q1 * sv;
                acc[2][t] += q2 * sv; acc[3][t] += q3 * sv;
            }
        }

        // rc[v][g][kl] = sum_{c<32} q[g][c]*pe[v][kl][c]
        for (int e = lane; e < 784; e += 32) {
            int v = e / 196, r2 = e - v * 196, gg = r2 / 49, kl = r2 - gg * 49;
            const float* per = pes + (v * 49 + kl) * 33;
            const float* qg  = qsi + gg * 48;
            float a = 0.f;
#pragma unroll
            for (int c = 0; c < 32; ++c) a += qg[c] * per[c];
            rc_s[e] = a;
        }
        __syncwarp();

        // softmax over (m,kl) per (v,g); accumulate probs over g into w
        const float inv_sqn = 0.17677669529663687f;   // 1/sqrt(32)
        for (int v = 0; v < 4; ++v) {
            for (int gg = 0; gg < 4; ++gg) {
                int vg = v * 4 + gg;
                float s[7];
                float mx = -1e30f;
#pragma unroll
                for (int t = 0; t < 7; ++t) {
                    if (valid[t]) {
                        s[t] = (acc[gg][t] + rc_s[vg * 49 + kl_t[t]]
                                + gs_s[vg * 4 + m_t[t]]) * inv_sqn;
                        mx = fmaxf(mx, s[t]);
                    } else s[t] = -1e30f;
                }
#pragma unroll
                for (int o = 16; o; o >>= 1) mx = fmaxf(mx, __shfl_xor_sync(0xffffffffu, mx, o));
                float sum = 0.f;
#pragma unroll
                for (int t = 0; t < 7; ++t) { s[t] = __expf(s[t] - mx); sum += s[t]; }
#pragma unroll
                for (int o = 16; o; o >>= 1) sum += __shfl_xor_sync(0xffffffffu, sum, o);
                float inv = 1.f / sum;
#pragma unroll
                for (int t = 0; t < 7; ++t) {
                    if (act[t]) {
                        int p = lane + 32 * t;
                        float pr = s[t] * inv;
                        if (gg == 0) w_s[p * 4 + v] = pr;
                        else         w_s[p * 4 + v] += pr;
                    }
                }
            }
        }
        __syncwarp();
    }
    __syncthreads();

    // =============== swap slab to v =========================================
    for (int i = tid; i < 19200; i += 256) {
        int c = i % 48, r = i / 48;
        int sx = r % 10, t2 = r / 10, sy = t2 % 10, m = t2 / 10;
        int y = ty0 - 3 + sy, xx = tx0 - 3 + sx;
        float val = 0.f;
        if ((unsigned)y < 28u && (unsigned)xx < 28u)
            val = g_v[((bh * 4 + m) * 784 + y * 28 + xx) * 48 + c];
        slab[c * 401 + m * 100 + sy * 10 + sx] = val;
    }
    __syncthreads();

    // =============== Phase 2: combine o[c][v] = sum_p w[p][v]*vslab[c][pos] =
    for (int si = 0; si < 2; ++si) {
        const int site = warp * 2 + si;
        const int ly = site >> 2, lx = site & 3;
        const float4* w4 = (const float4*)(scr + 784 + si * 784);
        const int yx = (ty0 + ly) * 28 + tx0 + lx;
#pragma unroll
        for (int pass = 0; pass < 2; ++pass) {
            int c = lane + pass * 32;
            if (c < 48) {
                float a0 = 0.f, a1 = 0.f, a2 = 0.f, a3 = 0.f;
                int p = 0;
#pragma unroll
                for (int m = 0; m < 4; ++m) {
#pragma unroll
                    for (int kk = 0; kk < 7; ++kk) {
                        const float* srow = slab + c * 401 + m * 100 + (ly + kk) * 10 + lx;
#pragma unroll
                        for (int ll = 0; ll < 7; ++ll) {
                            float sv = srow[ll];
                            float4 wv = w4[p];
                            a0 += wv.x * sv; a1 += wv.y * sv;
                            a2 += wv.z * sv; a3 += wv.w * sv;
                            ++p;
                        }
                    }
                }
                int ch = c * 4 + h;
                g_o[((b * 4 + 0) * 784 + yx) * 192 + ch] = a0;
                g_o[((b * 4 + 1) * 784 + yx) * 192 + ch] = a1;
                g_o[((b * 4 + 2) * 784 + yx) * 192 + ch] = a2;
                g_o[((b * 4 + 3) * 784 + yx) * 192 + ch] = a3;
            }
        }
    }
}

// ---------------------------------------------------------------------------
// out: out[b][o][v][yx] = sum_i Wout[o][i]*g_o[b][v][yx][i] + bout[o]
// 392 blocks x 256 threads; 16 sites/block; thread = (o4 group, site slot)
// Ws swizzled [i][o]: Ws[i*64 + (o ^ ((i&15)<<2))]
// ---------------------------------------------------------------------------
__global__ void __launch_bounds__(256) out_kernel(
    const float* __restrict__ Wout, const float* __restrict__ bout,
    float* __restrict__ out)
{
    extern __shared__ float Ws[];   // 12288 floats
    int tid = threadIdx.x;
    for (int idx = tid; idx < 12288; idx += 256) {
        int o = idx / 192, i = idx - o * 192;
        Ws[i * 64 + (o ^ ((i & 15) << 2))] = Wout[idx];
    }
    __syncthreads();

    int o4 = (tid & 15) * 4;
    int sl = tid >> 4;
    int site = blockIdx.x * 16 + sl;
    const float* go = g_o + site * 192;

    float a0 = bout[o4], a1 = bout[o4 + 1], a2 = bout[o4 + 2], a3 = bout[o4 + 3];
    for (int i = 0; i < 192; ++i) {
        float gv = go[i];
        int sw = (i & 15) << 2;
        float4 wv = *(const float4*)(Ws + i * 64 + (o4 ^ sw));
        a0 += wv.x * gv; a1 += wv.y * gv; a2 += wv.z * gv; a3 += wv.w * gv;
    }
    int bb = site / 3136, rem = site - bb * 3136;   // rem = v*784 + yx
    float* op = out + bb * 200704 + rem;
    op[(o4 + 0) * 3136] = a0;
    op[(o4 + 1) * 3136] = a1;
    op[(o4 + 2) * 3136] = a2;
    op[(o4 + 3) * 3136] = a3;
}

// ---------------------------------------------------------------------------
extern "C" void kernel_launch(void* const* d_in, const int* in_sizes, int n_in,
                              void* d_out, int out_size)
{
    const float* x    = (const float*)d_in[0];
    const float* Wq   = (const float*)d_in[1];  const float* bq = (const float*)d_in[2];
    const float* Wk   = (const float*)d_in[3];  const float* bk = (const float*)d_in[4];
    const float* Wv   = (const float*)d_in[5];  const float* bv = (const float*)d_in[6];
    const float* Wout = (const float*)d_in[7];  const float* bout = (const float*)d_in[8];
    const float* rw1  = (const float*)d_in[9];  const float* rb1 = (const float*)d_in[10];
    const float* rlg  = (const float*)d_in[11]; const float* rlb = (const float*)d_in[12];
    const float* rw2  = (const float*)d_in[13]; const float* rb2 = (const float*)d_in[14];
    const float* cw1  = (const float*)d_in[15]; const float* cb1 = (const float*)d_in[16];
    const float* clg  = (const float*)d_in[17]; const float* clb = (const float*)d_in[18];
    const float* cw2  = (const float*)d_in[19]; const float* cb2 = (const float*)d_in[20];
    const float* gemb = (const float*)d_in[21];
    const float* ridx = (const float*)d_in[22];
    const float* cidx = (const float*)d_in[23];
    const int*   gidx = (const int*)d_in[24];
    float* out = (float*)d_out;

    cudaFuncSetAttribute((const void*)attn_kernel,
                         cudaFuncAttributeMaxDynamicSharedMemorySize, ATTN_SMEM_BYTES);
    cudaFuncSetAttribute((const void*)out_kernel,
                         cudaFuncAttributeMaxDynamicSharedMemorySize, 49152);

    pe_kernel<<<1, 256>>>(rw1, rb1, rlg, rlb, rw2, rb2,
                          cw1, cb1, clg, clb, cw2, cb2,
                          ridx, cidx, gemb, gidx);
    proj_kernel<<<dim3(98, 9), 256>>>(x, Wq, bq, Wk, bk, Wv, bv);
    attn_kernel<<<392, 256, ATTN_SMEM_BYTES>>>();
    out_kernel<<<392, 256, 49152>>>(Wout, bout, out);
}

// round 3
// speedup vs baseline: 1.6900x; 1.6900x over previous
#include <cuda_runtime.h>
#include <math.h>

// Sizes: B=2, Cin=32, G=V=M=4, H=W=28, P=7, MID=48, HEADS=4, POS=16, Cout=64
// q/k/v layout: [(b*4+h)*4+g][yx][48c]
// g_pe: [v*49+kl][32c] (row 0..15, col 16..31)
// g_ge: [(v*4+g)*4+m][16c]
// g_o : [(b*4+v)*784+yx][192i]  with i = c*4+h

__device__ float g_q[1204224];
__device__ float g_k[1204224];
__device__ float g_v[1204224];
__device__ float g_pe[6272];
__device__ float g_ge[1024];
__device__ float g_o[1204224];

// ---------------------------------------------------------------------------
// PE MLP
// ---------------------------------------------------------------------------
__device__ __forceinline__ void pe_mlp(float tval,
    const float* __restrict__ w1, const float* __restrict__ b1,
    const float* __restrict__ lng, const float* __restrict__ lnb,
    const float* __restrict__ w2, const float* __restrict__ b2,
    float* outp)
{
    float hv[16];
    float mu = 0.f;
#pragma unroll
    for (int j = 0; j < 16; ++j) { hv[j] = tval * w1[j] + b1[j]; mu += hv[j]; }
    mu *= (1.f / 16.f);
    float var = 0.f;
#pragma unroll
    for (int j = 0; j < 16; ++j) { float d = hv[j] - mu; var += d * d; }
    var *= (1.f / 16.f);
    float rstd = rsqrtf(var + 1e-5f);
#pragma unroll
    for (int j = 0; j < 16; ++j) {
        float t = (hv[j] - mu) * rstd * lng[j] + lnb[j];
        hv[j] = t / (1.f + expf(-t));
    }
#pragma unroll
    for (int j = 0; j < 16; ++j) {
        float e = b2[j];
#pragma unroll
        for (int t = 0; t < 16; ++t) e += hv[t] * w2[j * 16 + t];
        outp[j] = e;
    }
}

__global__ void pe_kernel(
    const float* __restrict__ rw1, const float* __restrict__ rb1,
    const float* __restrict__ rlg, const float* __restrict__ rlb,
    const float* __restrict__ rw2, const float* __restrict__ rb2,
    const float* __restrict__ cw1, const float* __restrict__ cb1,
    const float* __restrict__ clg, const float* __restrict__ clb,
    const float* __restrict__ cw2, const float* __restrict__ cb2,
    const float* __restrict__ ridx, const float* __restrict__ cidx,
    const float* __restrict__ gemb, const int* __restrict__ gidx)
{
    int tid = threadIdx.x;
    if (tid < 196) {
        float er[16], ec[16];
        pe_mlp(ridx[tid], rw1, rb1, rlg, rlb, rw2, rb2, er);
        pe_mlp(cidx[tid], cw1, cb1, clg, clb, cw2, cb2, ec);
#pragma unroll
        for (int j = 0; j < 16; ++j) {
            g_pe[tid * 32 + j]      = er[j];
            g_pe[tid * 32 + 16 + j] = ec[j];
        }
    }
    for (int e = tid; e < 1024; e += blockDim.x) {
        int vgm = e >> 4, c = e & 15;
        g_ge[e] = gemb[gidx[vgm] * 16 + c];
    }
}

// ---------------------------------------------------------------------------
// proj: C[576 x 6272] = [Wq;Wk;Wv][576x32] * X[32x6272] -> g_q/k/v
// ---------------------------------------------------------------------------
__global__ void __launch_bounds__(256) proj_kernel(
    const float* __restrict__ x,
    const float* __restrict__ Wq, const float* __restrict__ bq,
    const float* __restrict__ Wk, const float* __restrict__ bk,
    const float* __restrict__ Wv, const float* __restrict__ bv)
{
    __shared__ float As[32 * 68];
    __shared__ float Bs[32 * 68];
    int tid = threadIdx.x;
    int n0 = blockIdx.x * 64;
    int r0 = blockIdx.y * 64;

#pragma unroll
    for (int k = 0; k < 8; ++k) {
        int i = tid + k * 256;
        int ci = i & 31, row = i >> 5;
        int rg = r0 + row;
        int which = rg / 192, r = rg - which * 192;
        const float* Wm = (which == 0) ? Wq : (which == 1 ? Wk : Wv);
        As[ci * 68 + row] = Wm[r * 32 + ci];
    }
#pragma unroll
    for (int k = 0; k < 8; ++k) {
        int i = tid + k * 256;
        int nl = i & 63, ci = i >> 6;
        int n = n0 + nl;
        int bb = n / 3136, rem = n - bb * 3136;
        Bs[ci * 68 + nl] = x[bb * 100352 + ci * 3136 + rem];
    }
    __syncthreads();

    int tx = tid & 15, ty = tid >> 4;
    float acc[4][4] = {};
#pragma unroll
    for (int ci = 0; ci < 32; ++ci) {
        float4 a4 = *(const float4*)&As[ci * 68 + ty * 4];
        float4 b4 = *(const float4*)&Bs[ci * 68 + tx * 4];
        float av[4] = { a4.x, a4.y, a4.z, a4.w };
        float bw[4] = { b4.x, b4.y, b4.z, b4.w };
#pragma unroll
        for (int u = 0; u < 4; ++u)
#pragma unroll
            for (int w = 0; w < 4; ++w) acc[u][w] += av[u] * bw[w];
    }

#pragma unroll
    for (int u = 0; u < 4; ++u) {
        int rg = r0 + ty * 4 + u;
        int which = rg / 192, r = rg - which * 192;
        int c = r >> 2, hh = r & 3;
        float bias = ((which == 0) ? bq : (which == 1 ? bk : bv))[r];
        float* dst = (which == 0) ? g_q : (which == 1 ? g_k : g_v);
#pragma unroll
        for (int w = 0; w < 4; ++w) {
            int n = n0 + tx * 4 + w;
            int bb = n / 3136, rem = n - bb * 3136;
            int gg = rem / 784, yx = rem - gg * 784;
            dst[(((bb * 4 + hh) * 4 + gg) * 784 + yx) * 48 + c] = acc[u][w] + bias;
        }
    }
}

// ---------------------------------------------------------------------------
// attn: one block per (b,h, 4x4 pixel tile). 512 threads = 16 warps = 1 site/warp.
// ---------------------------------------------------------------------------
#define SM_PE    0        // [196][36]  (float4-aligned rows)
#define SM_GE    7056     // [64][16]
#define SM_QS    8080     // [16 sites][4 g][48 c]
#define SM_SLAB  11152    // [48 c][401]  pos = m*100 + sy*10 + sx
#define SM_SCR   30400    // per-warp: rc 784 | w 784 | gs 64 = 1632
#define SCR_WARP 1632
#define ATTN_SMEM_FLOATS (SM_SCR + 16 * SCR_WARP)  // 56512
#define ATTN_SMEM_BYTES  (ATTN_SMEM_FLOATS * 4)    // 226048

__global__ void __launch_bounds__(512, 1) attn_kernel()
{
    extern __shared__ float sm[];
    float* pes  = sm + SM_PE;
    float* ges  = sm + SM_GE;
    float* qs   = sm + SM_QS;
    float* slab = sm + SM_SLAB;

    const int tid  = threadIdx.x, lane = tid & 31, warp = tid >> 5;
    const int tile = blockIdx.x % 49;
    const int bh   = blockIdx.x / 49;
    const int b    = bh >> 2, h = bh & 3;
    const int ty0  = (tile / 7) * 4, tx0 = (tile % 7) * 4;

    for (int i = tid; i < 6272; i += 512) pes[(i >> 5) * 36 + (i & 31)] = g_pe[i];
    for (int i = tid; i < 1024; i += 512) ges[i] = g_ge[i];
    for (int i = tid; i < 3072; i += 512) {
        int site = i / 192, r = i - site * 192, gg = r / 48, c = r - gg * 48;
        int yx = (ty0 + (site >> 2)) * 28 + tx0 + (site & 3);
        qs[i] = g_q[((bh * 4 + gg) * 784 + yx) * 48 + c];
    }
    for (int i = tid; i < 19200; i += 512) {
        int c = i % 48, r = i / 48;
        int sx = r % 10, t2 = r / 10, sy = t2 % 10, m = t2 / 10;
        int y = ty0 - 3 + sy, xx = tx0 - 3 + sx;
        float val = 0.f;
        if ((unsigned)y < 28u && (unsigned)xx < 28u)
            val = g_k[((bh * 4 + m) * 784 + y * 28 + xx) * 48 + c];
        slab[c * 401 + m * 100 + sy * 10 + sx] = val;
    }
    __syncthreads();

    float* scr  = sm + SM_SCR + warp * SCR_WARP;
    float* rc_s = scr;            // 784: [v][g][49 kl]
    float* w_s  = scr + 784;      // 784: [196 p][4 v]
    float* gs_s = scr + 1568;     // 64 : [v][g][4 m]

    const int site = warp;
    const int ly = site >> 2, lx = site & 3;
    const float* qsi = qs + site * 192;

    // =============== Phase 1: scores + softmax -> w[p][4v] =================
    // group scores gs[v][g][m]
#pragma unroll
    for (int u = 0; u < 2; ++u) {
        int e = lane * 2 + u;
        int gg = (e >> 2) & 3;
        float a = 0.f;
#pragma unroll
        for (int c = 0; c < 16; ++c)
            a += qsi[gg * 48 + 32 + c] * ges[e * 16 + c];
        gs_s[e] = a;
    }

    // per-lane entry mapping: p = lane + 32*t over 196 = 4m x 49kl
    int kl_t[7], m_t[7], pos_t[7];
    bool valid[7], act[7];
#pragma unroll
    for (int t = 0; t < 7; ++t) {
        int p = lane + 32 * t;
        act[t] = (p < 196);
        int pc = act[t] ? p : 0;
        int m = pc / 49, kl = pc - m * 49, kk = kl / 7, ll = kl - kk * 7;
        kl_t[t] = kl; m_t[t] = m;
        pos_t[t] = m * 100 + (ly + kk) * 10 + (lx + ll);
        int y = ty0 + ly + kk - 3, xx = tx0 + lx + ll - 3;
        valid[t] = act[t] && ((unsigned)y < 28u) && ((unsigned)xx < 28u);
    }

    // content[g][t] = sum_c q[g][c] * k_slab[c][pos_t]
    float acc[4][7];
#pragma unroll
    for (int gg = 0; gg < 4; ++gg)
#pragma unroll
        for (int t = 0; t < 7; ++t) acc[gg][t] = 0.f;
    {
        const float4* q4p = (const float4*)qsi;
        for (int c4 = 0; c4 < 12; ++c4) {
            float4 qa = q4p[c4], qb = q4p[12 + c4], qc = q4p[24 + c4], qd = q4p[36 + c4];
            float qr[4][4] = { { qa.x, qa.y, qa.z, qa.w },
                               { qb.x, qb.y, qb.z, qb.w },
                               { qc.x, qc.y, qc.z, qc.w },
                               { qd.x, qd.y, qd.z, qd.w } };
#pragma unroll
            for (int u = 0; u < 4; ++u) {
                const float* sr = slab + (c4 * 4 + u) * 401;
#pragma unroll
                for (int t = 0; t < 7; ++t) {
                    float sv = sr[pos_t[t]];
                    acc[0][t] += qr[0][u] * sv; acc[1][t] += qr[1][u] * sv;
                    acc[2][t] += qr[2][u] * sv; acc[3][t] += qr[3][u] * sv;
                }
            }
        }
    }

    // rc[v][g][kl] = sum_{c<32} q[g][c]*pe[v][kl][c]   (float4)
    for (int e = lane; e < 784; e += 32) {
        int v = e / 196, r2 = e - v * 196, gg = r2 / 49, kl = r2 - gg * 49;
        const float4* per = (const float4*)(pes + (v * 49 + kl) * 36);
        const float4* qg4 = (const float4*)(qsi + gg * 48);
        float a = 0.f;
#pragma unroll
        for (int c4 = 0; c4 < 8; ++c4) {
            float4 p4 = per[c4], q4 = qg4[c4];
            a += p4.x * q4.x + p4.y * q4.y + p4.z * q4.z + p4.w * q4.w;
        }
        rc_s[e] = a;
    }
    __syncwarp();

    // softmax over (m,kl) per (v,g); fold probs over g in registers
    const float inv_sqn = 0.17677669529663687f;   // 1/sqrt(32)
    for (int v = 0; v < 4; ++v) {
        float wacc[7];
#pragma unroll
        for (int t = 0; t < 7; ++t) wacc[t] = 0.f;
        for (int gg = 0; gg < 4; ++gg) {
            int vg = v * 4 + gg;
            float s[7];
            float mx = -1e30f;
#pragma unroll
            for (int t = 0; t < 7; ++t) {
                if (valid[t]) {
                    s[t] = (acc[gg][t] + rc_s[vg * 49 + kl_t[t]]
                            + gs_s[vg * 4 + m_t[t]]) * inv_sqn;
                    mx = fmaxf(mx, s[t]);
                } else s[t] = -1e30f;
            }
#pragma unroll
            for (int o = 16; o; o >>= 1) mx = fmaxf(mx, __shfl_xor_sync(0xffffffffu, mx, o));
            float sum = 0.f;
#pragma unroll
            for (int t = 0; t < 7; ++t) { s[t] = __expf(s[t] - mx); sum += s[t]; }
#pragma unroll
            for (int o = 16; o; o >>= 1) sum += __shfl_xor_sync(0xffffffffu, sum, o);
            float inv = 1.f / sum;
#pragma unroll
            for (int t = 0; t < 7; ++t) wacc[t] += s[t] * inv;
        }
#pragma unroll
        for (int t = 0; t < 7; ++t)
            if (act[t]) w_s[(lane + 32 * t) * 4 + v] = wacc[t];
    }
    __syncthreads();

    // =============== swap slab to v =========================================
    for (int i = tid; i < 19200; i += 512) {
        int c = i % 48, r = i / 48;
        int sx = r % 10, t2 = r / 10, sy = t2 % 10, m = t2 / 10;
        int y = ty0 - 3 + sy, xx = tx0 - 3 + sx;
        float val = 0.f;
        if ((unsigned)y < 28u && (unsigned)xx < 28u)
            val = g_v[((bh * 4 + m) * 784 + y * 28 + xx) * 48 + c];
        slab[c * 401 + m * 100 + sy * 10 + sx] = val;
    }
    __syncthreads();

    // =============== Phase 2: combine o[c][v] = sum_p w[p][v]*vslab[c][pos] =
    {
        const float4* w4 = (const float4*)w_s;
        const int yx = (ty0 + ly) * 28 + tx0 + lx;
#pragma unroll
        for (int pass = 0; pass < 2; ++pass) {
            int c = lane + pass * 32;
            if (c < 48) {
                float a0 = 0.f, a1 = 0.f, a2 = 0.f, a3 = 0.f;
                for (int m = 0; m < 4; ++m) {
#pragma unroll
                    for (int kk = 0; kk < 7; ++kk) {
                        const float* srow = slab + c * 401 + m * 100 + (ly + kk) * 10 + lx;
                        int p = m * 49 + kk * 7;
#pragma unroll
                        for (int ll = 0; ll < 7; ++ll) {
                            float sv = srow[ll];
                            float4 wv = w4[p + ll];
                            a0 += wv.x * sv; a1 += wv.y * sv;
                            a2 += wv.z * sv; a3 += wv.w * sv;
                        }
                    }
                }
                int ch = c * 4 + h;
                g_o[((b * 4 + 0) * 784 + yx) * 192 + ch] = a0;
                g_o[((b * 4 + 1) * 784 + yx) * 192 + ch] = a1;
                g_o[((b * 4 + 2) * 784 + yx) * 192 + ch] = a2;
                g_o[((b * 4 + 3) * 784 + yx) * 192 + ch] = a3;
            }
        }
    }
}

// ---------------------------------------------------------------------------
// out: out[b][o][v][yx] = sum_i Wout[o][i]*g_o[site][i] + bout[o]
// 392 blocks x 256 threads; thread = (o-group = tid>>4, site slot = tid&15)
// g_o block staged in SMEM transposed (stride 17) for conflict-free broadcast.
// ---------------------------------------------------------------------------
#define OUT_SMEM_FLOATS (12288 + 192 * 17 + 16)
#define OUT_SMEM_BYTES  (OUT_SMEM_FLOATS * 4)

__global__ void __launch_bounds__(256) out_kernel(
    const float* __restrict__ Wout, const float* __restrict__ bout,
    float* __restrict__ out)
{
    extern __shared__ float smo[];
    float* Ws = smo;              // [192 i][64 o] xor-swizzled
    float* Gs = smo + 12288;      // [192 i][17] (site in low dim)
    int tid = threadIdx.x;
    for (int idx = tid; idx < 12288; idx += 256) {
        int o = idx / 192, i = idx - o * 192;
        Ws[i * 64 + (o ^ ((i & 15) << 2))] = Wout[idx];
    }
    const float4* gsrc = (const float4*)(g_o + blockIdx.x * 3072);
    for (int idx = tid; idx < 768; idx += 256) {
        float4 vv = gsrc[idx];
        int site = idx / 48, off = (idx - site * 48) * 4;
        Gs[(off + 0) * 17 + site] = vv.x;
        Gs[(off + 1) * 17 + site] = vv.y;
        Gs[(off + 2) * 17 + site] = vv.z;
        Gs[(off + 3) * 17 + site] = vv.w;
    }
    __syncthreads();

    int o4 = (tid >> 4) * 4;
    int sl = tid & 15;
    float a0 = bout[o4], a1 = bout[o4 + 1], a2 = bout[o4 + 2], a3 = bout[o4 + 3];
#pragma unroll 8
    for (int i = 0; i < 192; ++i) {
        float gv = Gs[i * 17 + sl];
        float4 wv = *(const float4*)(Ws + i * 64 + (o4 ^ ((i & 15) << 2)));
        a0 += wv.x * gv; a1 += wv.y * gv; a2 += wv.z * gv; a3 += wv.w * gv;
    }
    int site = blockIdx.x * 16 + sl;
    int bb = site / 3136, rem = site - bb * 3136;
    float* op = out + bb * 200704 + rem;
    op[(o4 + 0) * 3136] = a0;
    op[(o4 + 1) * 3136] = a1;
    op[(o4 + 2) * 3136] = a2;
    op[(o4 + 3) * 3136] = a3;
}

// ---------------------------------------------------------------------------
extern "C" void kernel_launch(void* const* d_in, const int* in_sizes, int n_in,
                              void* d_out, int out_size)
{
    const float* x    = (const float*)d_in[0];
    const float* Wq   = (const float*)d_in[1];  const float* bq = (const float*)d_in[2];
    const float* Wk   = (const float*)d_in[3];  const float* bk = (const float*)d_in[4];
    const float* Wv   = (const float*)d_in[5];  const float* bv = (const float*)d_in[6];
    const float* Wout = (const float*)d_in[7];  const float* bout = (const float*)d_in[8];
    const float* rw1  = (const float*)d_in[9];  const float* rb1 = (const float*)d_in[10];
    const float* rlg  = (const float*)d_in[11]; const float* rlb = (const float*)d_in[12];
    const float* rw2  = (const float*)d_in[13]; const float* rb2 = (const float*)d_in[14];
    const float* cw1  = (const float*)d_in[15]; const float* cb1 = (const float*)d_in[16];
    const float* clg  = (const float*)d_in[17]; const float* clb = (const float*)d_in[18];
    const float* cw2  = (const float*)d_in[19]; const float* cb2 = (const float*)d_in[20];
    const float* gemb = (const float*)d_in[21];
    const float* ridx = (const float*)d_in[22];
    const float* cidx = (const float*)d_in[23];
    const int*   gidx = (const int*)d_in[24];
    float* out = (float*)d_out;

    cudaFuncSetAttribute((const void*)attn_kernel,
                         cudaFuncAttributeMaxDynamicSharedMemorySize, ATTN_SMEM_BYTES);
    cudaFuncSetAttribute((const void*)out_kernel,
                         cudaFuncAttributeMaxDynamicSharedMemorySize, OUT_SMEM_BYTES);

    pe_kernel<<<1, 256>>>(rw1, rb1, rlg, rlb, rw2, rb2,
                          cw1, cb1, clg, clb, cw2, cb2,
                          ridx, cidx, gemb, gidx);
    proj_kernel<<<dim3(98, 9), 256>>>(x, Wq, bq, Wk, bk, Wv, bv);
    attn_kernel<<<392, 512, ATTN_SMEM_BYTES>>>();
    out_kernel<<<392, 256, OUT_SMEM_BYTES>>>(Wout, bout, out);
}

// round 4
// speedup vs baseline: 2.1627x; 1.2797x over previous
#include <cuda_runtime.h>
#include <math.h>

// Sizes: B=2, Cin=32, G=V=M=4, H=W=28, P=7, MID=48, HEADS=4, POS=16, Cout=64
// q/k/v layout: [(b*4+h)*4+g][yx][48c]
// g_pe: [v*49+kl][32c] (row 0..15, col 16..31)
// g_ge: [(v*4+g)*4+m][16c]
// g_o : [(b*4+v)*784+yx][192i]  with i = c*4+h

__device__ float g_q[1204224];
__device__ float g_k[1204224];
__device__ float g_v[1204224];
__device__ float g_pe[6272];
__device__ float g_ge[1024];
__device__ float g_o[1204224];

// ---------------------------------------------------------------------------
// PE MLP
// ---------------------------------------------------------------------------
__device__ __forceinline__ void pe_mlp(float tval,
    const float* __restrict__ w1, const float* __restrict__ b1,
    const float* __restrict__ lng, const float* __restrict__ lnb,
    const float* __restrict__ w2, const float* __restrict__ b2,
    float* outp)
{
    float hv[16];
    float mu = 0.f;
#pragma unroll
    for (int j = 0; j < 16; ++j) { hv[j] = tval * w1[j] + b1[j]; mu += hv[j]; }
    mu *= (1.f / 16.f);
    float var = 0.f;
#pragma unroll
    for (int j = 0; j < 16; ++j) { float d = hv[j] - mu; var += d * d; }
    var *= (1.f / 16.f);
    float rstd = rsqrtf(var + 1e-5f);
#pragma unroll
    for (int j = 0; j < 16; ++j) {
        float t = (hv[j] - mu) * rstd * lng[j] + lnb[j];
        hv[j] = t / (1.f + expf(-t));
    }
#pragma unroll
    for (int j = 0; j < 16; ++j) {
        float e = b2[j];
#pragma unroll
        for (int t = 0; t < 16; ++t) e += hv[t] * w2[j * 16 + t];
        outp[j] = e;
    }
}

__global__ void pe_kernel(
    const float* __restrict__ rw1, const float* __restrict__ rb1,
    const float* __restrict__ rlg, const float* __restrict__ rlb,
    const float* __restrict__ rw2, const float* __restrict__ rb2,
    const float* __restrict__ cw1, const float* __restrict__ cb1,
    const float* __restrict__ clg, const float* __restrict__ clb,
    const float* __restrict__ cw2, const float* __restrict__ cb2,
    const float* __restrict__ ridx, const float* __restrict__ cidx,
    const float* __restrict__ gemb, const int* __restrict__ gidx)
{
    int tid = threadIdx.x;
    if (tid < 196) {
        float er[16], ec[16];
        pe_mlp(ridx[tid], rw1, rb1, rlg, rlb, rw2, rb2, er);
        pe_mlp(cidx[tid], cw1, cb1, clg, clb, cw2, cb2, ec);
#pragma unroll
        for (int j = 0; j < 16; ++j) {
            g_pe[tid * 32 + j]      = er[j];
            g_pe[tid * 32 + 16 + j] = ec[j];
        }
    }
    for (int e = tid; e < 1024; e += blockDim.x) {
        int vgm = e >> 4, c = e & 15;
        g_ge[e] = gemb[gidx[vgm] * 16 + c];
    }
}

// ---------------------------------------------------------------------------
// proj: C[576 x 6272] = [Wq;Wk;Wv][576x32] * X[32x6272] -> g_q/k/v
// ---------------------------------------------------------------------------
__global__ void __launch_bounds__(256) proj_kernel(
    const float* __restrict__ x,
    const float* __restrict__ Wq, const float* __restrict__ bq,
    const float* __restrict__ Wk, const float* __restrict__ bk,
    const float* __restrict__ Wv, const float* __restrict__ bv)
{
    __shared__ float As[32 * 68];
    __shared__ float Bs[32 * 68];
    int tid = threadIdx.x;
    int n0 = blockIdx.x * 64;
    int r0 = blockIdx.y * 64;

#pragma unroll
    for (int k = 0; k < 8; ++k) {
        int i = tid + k * 256;
        int ci = i & 31, row = i >> 5;
        int rg = r0 + row;
        int which = rg / 192, r = rg - which * 192;
        const float* Wm = (which == 0) ? Wq : (which == 1 ? Wk : Wv);
        As[ci * 68 + row] = Wm[r * 32 + ci];
    }
#pragma unroll
    for (int k = 0; k < 8; ++k) {
        int i = tid + k * 256;
        int nl = i & 63, ci = i >> 6;
        int n = n0 + nl;
        int bb = n / 3136, rem = n - bb * 3136;
        Bs[ci * 68 + nl] = x[bb * 100352 + ci * 3136 + rem];
    }
    __syncthreads();

    int tx = tid & 15, ty = tid >> 4;
    float acc[4][4] = {};
#pragma unroll
    for (int ci = 0; ci < 32; ++ci) {
        float4 a4 = *(const float4*)&As[ci * 68 + ty * 4];
        float4 b4 = *(const float4*)&Bs[ci * 68 + tx * 4];
        float av[4] = { a4.x, a4.y, a4.z, a4.w };
        float bw[4] = { b4.x, b4.y, b4.z, b4.w };
#pragma unroll
        for (int u = 0; u < 4; ++u)
#pragma unroll
            for (int w = 0; w < 4; ++w) acc[u][w] += av[u] * bw[w];
    }

#pragma unroll
    for (int u = 0; u < 4; ++u) {
        int rg = r0 + ty * 4 + u;
        int which = rg / 192, r = rg - which * 192;
        int c = r >> 2, hh = r & 3;
        float bias = ((which == 0) ? bq : (which == 1 ? bk : bv))[r];
        float* dst = (which == 0) ? g_q : (which == 1 ? g_k : g_v);
#pragma unroll
        for (int w = 0; w < 4; ++w) {
            int n = n0 + tx * 4 + w;
            int bb = n / 3136, rem = n - bb * 3136;
            int gg = rem / 784, yx = rem - gg * 784;
            dst[(((bb * 4 + hh) * 4 + gg) * 784 + yx) * 48 + c] = acc[u][w] + bias;
        }
    }
}

// ---------------------------------------------------------------------------
// attn: one block per (b,h, 4x4 pixel tile). 512 threads = 16 warps = 1 site/warp.
// ---------------------------------------------------------------------------
#define SM_PE    0        // [196][36]  (float4-aligned rows)
#define SM_GE    7056     // [64][16]
#define SM_QS    8080     // [16 sites][4 g][48 c]
#define SM_SLAB  11152    // [48 c][401]  pos = m*100 + sy*10 + sx
#define SM_SCR   30400    // per-warp: rc 784 | w 784 | gs 64 = 1632
#define SCR_WARP 1632
#define ATTN_SMEM_FLOATS (SM_SCR + 16 * SCR_WARP)  // 56512
#define ATTN_SMEM_BYTES  (ATTN_SMEM_FLOATS * 4)    // 226048

// slab loader: thread = (c = tid%48, sx = tid/48), walk m,sy with constant
// offsets. 480 active threads, 40 predicated LDG+STS each, coalesced over c.
__device__ __forceinline__ void load_slab(float* slab, const float* __restrict__ src,
                                          int bh, int ty0, int tx0, int tid)
{
    if (tid < 480) {
        int c  = tid % 48;
        int sx = tid / 48;                       // 0..9
        int xx = tx0 - 3 + sx;
        bool xok = (unsigned)xx < 28u;
        float* sdst = slab + c * 401 + sx;
        const float* gbase = src + (bh * 4) * 37632 + xx * 48 + c;  // + m*37632 + y*1344
#pragma unroll
        for (int m = 0; m < 4; ++m) {
#pragma unroll
            for (int sy = 0; sy < 10; ++sy) {
                int y = ty0 - 3 + sy;
                float val = 0.f;
                if (xok && (unsigned)y < 28u)
                    val = gbase[m * 37632 + y * 1344];
                sdst[m * 100 + sy * 10] = val;
            }
        }
    }
}

__global__ void __launch_bounds__(512, 1) attn_kernel()
{
    extern __shared__ float sm[];
    float* pes  = sm + SM_PE;
    float* ges  = sm + SM_GE;
    float* qs   = sm + SM_QS;
    float* slab = sm + SM_SLAB;

    const int tid  = threadIdx.x, lane = tid & 31, warp = tid >> 5;
    const int tile = blockIdx.x % 49;
    const int bh   = blockIdx.x / 49;
    const int b    = bh >> 2, h = bh & 3;
    const int ty0  = (tile / 7) * 4, tx0 = (tile % 7) * 4;

    for (int i = tid; i < 6272; i += 512) pes[(i >> 5) * 36 + (i & 31)] = g_pe[i];
    for (int i = tid; i < 1024; i += 512) ges[i] = g_ge[i];
    for (int i = tid; i < 3072; i += 512) {
        int site = i / 192, r = i - site * 192, gg = r / 48, c = r - gg * 48;
        int yx = (ty0 + (site >> 2)) * 28 + tx0 + (site & 3);
        qs[i] = g_q[((bh * 4 + gg) * 784 + yx) * 48 + c];
    }
    load_slab(slab, g_k, bh, ty0, tx0, tid);
    __syncthreads();

    float* scr  = sm + SM_SCR + warp * SCR_WARP;
    float* rc_s = scr;            // 784: [v][g][49 kl]
    float* w_s  = scr + 784;      // 784: [196 p][4 v]
    float* gs_s = scr + 1568;     // 64 : [v][g][4 m]

    const int site = warp;
    const int ly = site >> 2, lx = site & 3;
    const float* qsi = qs + site * 192;

    // =============== Phase 1: scores + softmax -> w[p][4v] =================
    // group scores gs[v][g][m]
#pragma unroll
    for (int u = 0; u < 2; ++u) {
        int e = lane * 2 + u;
        int gg = (e >> 2) & 3;
        float a = 0.f;
#pragma unroll
        for (int c = 0; c < 16; ++c)
            a += qsi[gg * 48 + 32 + c] * ges[e * 16 + c];
        gs_s[e] = a;
    }

    // per-lane entry mapping: p = lane + 32*t over 196 = 4m x 49kl
    int kl_t[7], m_t[7], pos_t[7];
    bool valid[7], act[7];
#pragma unroll
    for (int t = 0; t < 7; ++t) {
        int p = lane + 32 * t;
        act[t] = (p < 196);
        int pc = act[t] ? p : 0;
        int m = pc / 49, kl = pc - m * 49, kk = kl / 7, ll = kl - kk * 7;
        kl_t[t] = kl; m_t[t] = m;
        pos_t[t] = m * 100 + (ly + kk) * 10 + (lx + ll);
        int y = ty0 + ly + kk - 3, xx = tx0 + lx + ll - 3;
        valid[t] = act[t] && ((unsigned)y < 28u) && ((unsigned)xx < 28u);
    }

    // content[g][t] = sum_c q[g][c] * k_slab[c][pos_t]
    float acc[4][7];
#pragma unroll
    for (int gg = 0; gg < 4; ++gg)
#pragma unroll
        for (int t = 0; t < 7; ++t) acc[gg][t] = 0.f;
    {
        const float4* q4p = (const float4*)qsi;
        for (int c4 = 0; c4 < 12; ++c4) {
            float4 qa = q4p[c4], qb = q4p[12 + c4], qc = q4p[24 + c4], qd = q4p[36 + c4];
            float qr[4][4] = { { qa.x, qa.y, qa.z, qa.w },
                               { qb.x, qb.y, qb.z, qb.w },
                               { qc.x, qc.y, qc.z, qc.w },
                               { qd.x, qd.y, qd.z, qd.w } };
#pragma unroll
            for (int u = 0; u < 4; ++u) {
                const float* sr = slab + (c4 * 4 + u) * 401;
#pragma unroll
                for (int t = 0; t < 7; ++t) {
                    float sv = sr[pos_t[t]];
                    acc[0][t] += qr[0][u] * sv; acc[1][t] += qr[1][u] * sv;
                    acc[2][t] += qr[2][u] * sv; acc[3][t] += qr[3][u] * sv;
                }
            }
        }
    }

    // rc[v][g][kl] = sum_{c<32} q[g][c]*pe[v][kl][c]
    // g-outer: q[g][0..31] hoisted into registers (uniform -> broadcast LDS);
    // pe streamed float4 per-lane (stride 36 -> conflict-free phases).
#pragma unroll 1
    for (int gg = 0; gg < 4; ++gg) {
        float qreg[32];
        const float4* qg4 = (const float4*)(qsi + gg * 48);
#pragma unroll
        for (int j = 0; j < 8; ++j) {
            float4 tq = qg4[j];
            qreg[j * 4 + 0] = tq.x; qreg[j * 4 + 1] = tq.y;
            qreg[j * 4 + 2] = tq.z; qreg[j * 4 + 3] = tq.w;
        }
        for (int e = lane; e < 196; e += 32) {       // e = v*49 + kl
            const float4* per = (const float4*)(pes + e * 36);
            float a = 0.f;
#pragma unroll
            for (int c4 = 0; c4 < 8; ++c4) {
                float4 p4 = per[c4];
                a += p4.x * qreg[c4 * 4 + 0] + p4.y * qreg[c4 * 4 + 1]
                   + p4.z * qreg[c4 * 4 + 2] + p4.w * qreg[c4 * 4 + 3];
            }
            int v = e / 49, kl = e - v * 49;
            rc_s[(v * 4 + gg) * 49 + kl] = a;
        }
    }
    __syncwarp();

    // softmax over (m,kl) per (v,g); g-pairs interleaved for latency overlap
    const float inv_sqn = 0.17677669529663687f;   // 1/sqrt(32)
    for (int v = 0; v < 4; ++v) {
        float wacc[7];
#pragma unroll
        for (int t = 0; t < 7; ++t) wacc[t] = 0.f;
#pragma unroll 1
        for (int gp = 0; gp < 2; ++gp) {
            int g0 = gp * 2, g1 = gp * 2 + 1;
            int vg0 = v * 4 + g0, vg1 = v * 4 + g1;
            float s0[7], s1[7];
            float mx0 = -1e30f, mx1 = -1e30f;
#pragma unroll
            for (int t = 0; t < 7; ++t) {
                if (valid[t]) {
                    float base_r0 = rc_s[vg0 * 49 + kl_t[t]];
                    float base_r1 = rc_s[vg1 * 49 + kl_t[t]];
                    s0[t] = (acc[g0][t] + base_r0 + gs_s[vg0 * 4 + m_t[t]]) * inv_sqn;
                    s1[t] = (acc[g1][t] + base_r1 + gs_s[vg1 * 4 + m_t[t]]) * inv_sqn;
                    mx0 = fmaxf(mx0, s0[t]); mx1 = fmaxf(mx1, s1[t]);
                } else { s0[t] = -1e30f; s1[t] = -1e30f; }
            }
#pragma unroll
            for (int o = 16; o; o >>= 1) {
                mx0 = fmaxf(mx0, __shfl_xor_sync(0xffffffffu, mx0, o));
                mx1 = fmaxf(mx1, __shfl_xor_sync(0xffffffffu, mx1, o));
            }
            float sum0 = 0.f, sum1 = 0.f;
#pragma unroll
            for (int t = 0; t < 7; ++t) {
                s0[t] = __expf(s0[t] - mx0); sum0 += s0[t];
                s1[t] = __expf(s1[t] - mx1); sum1 += s1[t];
            }
#pragma unroll
            for (int o = 16; o; o >>= 1) {
                sum0 += __shfl_xor_sync(0xffffffffu, sum0, o);
                sum1 += __shfl_xor_sync(0xffffffffu, sum1, o);
            }
            float inv0 = 1.f / sum0, inv1 = 1.f / sum1;
#pragma unroll
            for (int t = 0; t < 7; ++t)
                wacc[t] += s0[t] * inv0 + s1[t] * inv1;
        }
#pragma unroll
        for (int t = 0; t < 7; ++t)
            if (act[t]) w_s[(lane + 32 * t) * 4 + v] = wacc[t];
    }
    __syncthreads();

    // =============== swap slab to v =========================================
    load_slab(slab, g_v, bh, ty0, tx0, tid);
    __syncthreads();

    // =============== Phase 2: combine o[c][v] = sum_p w[p][v]*vslab[c][pos] =
    {
        const float4* w4 = (const float4*)w_s;
        const int yx = (ty0 + ly) * 28 + tx0 + lx;
#pragma unroll
        for (int pass = 0; pass < 2; ++pass) {
            int c = lane + pass * 32;
            if (c < 48) {
                float a0 = 0.f, a1 = 0.f, a2 = 0.f, a3 = 0.f;
                for (int m = 0; m < 4; ++m) {
#pragma unroll
                    for (int kk = 0; kk < 7; ++kk) {
                        const float* srow = slab + c * 401 + m * 100 + (ly + kk) * 10 + lx;
                        int p = m * 49 + kk * 7;
#pragma unroll
                        for (int ll = 0; ll < 7; ++ll) {
                            float sv = srow[ll];
                            float4 wv = w4[p + ll];
                            a0 += wv.x * sv; a1 += wv.y * sv;
                            a2 += wv.z * sv; a3 += wv.w * sv;
                        }
                    }
                }
                int ch = c * 4 + h;
                g_o[((b * 4 + 0) * 784 + yx) * 192 + ch] = a0;
                g_o[((b * 4 + 1) * 784 + yx) * 192 + ch] = a1;
                g_o[((b * 4 + 2) * 784 + yx) * 192 + ch] = a2;
                g_o[((b * 4 + 3) * 784 + yx) * 192 + ch] = a3;
            }
        }
    }
}

// ---------------------------------------------------------------------------
// out: out[b][o][v][yx] = sum_i Wout[o][i]*g_o[site][i] + bout[o]
// 196 blocks x 512 threads; 32 sites/block; warp = one o4-group over 32 sites.
// Ws[i*68+o] (transposed, pad 68) -> warp-uniform float4 broadcast reads.
// Gs[i*33+site] -> conflict-free per-lane reads.
// ---------------------------------------------------------------------------
#define OUT_SMEM_FLOATS (192 * 68 + 192 * 33)
#define OUT_SMEM_BYTES  (OUT_SMEM_FLOATS * 4)

__global__ void __launch_bounds__(512) out_kernel(
    const float* __restrict__ Wout, const float* __restrict__ bout,
    float* __restrict__ out)
{
    extern __shared__ float smo[];
    float* Ws = smo;                  // [192 i][68] (o in low dim)
    float* Gs = smo + 192 * 68;      // [192 i][33] (site in low dim)
    int tid = threadIdx.x;
    for (int idx = tid; idx < 12288; idx += 512) {
        int o = idx / 192, i = idx - o * 192;
        Ws[i * 68 + o] = Wout[idx];
    }
    const float4* gsrc = (const float4*)(g_o + blockIdx.x * 6144);
    for (int idx = tid; idx < 1536; idx += 512) {
        float4 vv = gsrc[idx];
        int site = idx / 48, off = (idx - site * 48) * 4;
        Gs[(off + 0) * 33 + site] = vv.x;
        Gs[(off + 1) * 33 + site] = vv.y;
        Gs[(off + 2) * 33 + site] = vv.z;
        Gs[(off + 3) * 33 + site] = vv.w;
    }
    __syncthreads();

    int o4 = (tid >> 5) * 4;      // uniform per warp
    int sl = tid & 31;
    float a0 = bout[o4], a1 = bout[o4 + 1], a2 = bout[o4 + 2], a3 = bout[o4 + 3];
#pragma unroll 8
    for (int i = 0; i < 192; ++i) {
        float gv = Gs[i * 33 + sl];
        float4 wv = *(const float4*)(Ws + i * 68 + o4);
        a0 += wv.x * gv; a1 += wv.y * gv; a2 += wv.z * gv; a3 += wv.w * gv;
    }
    int site = blockIdx.x * 32 + sl;
    int bb = site / 3136, rem = site - bb * 3136;
    float* op = out + bb * 200704 + rem;
    op[(o4 + 0) * 3136] = a0;
    op[(o4 + 1) * 3136] = a1;
    op[(o4 + 2) * 3136] = a2;
    op[(o4 + 3) * 3136] = a3;
}

// ---------------------------------------------------------------------------
extern "C" void kernel_launch(void* const* d_in, const int* in_sizes, int n_in,
                              void* d_out, int out_size)
{
    const float* x    = (const float*)d_in[0];
    const float* Wq   = (const float*)d_in[1];  const float* bq = (const float*)d_in[2];
    const float* Wk   = (const float*)d_in[3];  const float* bk = (const float*)d_in[4];
    const float* Wv   = (const float*)d_in[5];  const float* bv = (const float*)d_in[6];
    const float* Wout = (const float*)d_in[7];  const float* bout = (const float*)d_in[8];
    const float* rw1  = (const float*)d_in[9];  const float* rb1 = (const float*)d_in[10];
    const float* rlg  = (const float*)d_in[11]; const float* rlb = (const float*)d_in[12];
    const float* rw2  = (const float*)d_in[13]; const float* rb2 = (const float*)d_in[14];
    const float* cw1  = (const float*)d_in[15]; const float* cb1 = (const float*)d_in[16];
    const float* clg  = (const float*)d_in[17]; const float* clb = (const float*)d_in[18];
    const float* cw2  = (const float*)d_in[19]; const float* cb2 = (const float*)d_in[20];
    const float* gemb = (const float*)d_in[21];
    const float* ridx = (const float*)d_in[22];
    const float* cidx = (const float*)d_in[23];
    const int*   gidx = (const int*)d_in[24];
    float* out = (float*)d_out;

    cudaFuncSetAttribute((const void*)attn_kernel,
                         cudaFuncAttributeMaxDynamicSharedMemorySize, ATTN_SMEM_BYTES);
    cudaFuncSetAttribute((const void*)out_kernel,
                         cudaFuncAttributeMaxDynamicSharedMemorySize, OUT_SMEM_BYTES);

    pe_kernel<<<1, 256>>>(rw1, rb1, rlg, rlb, rw2, rb2,
                          cw1, cb1, clg, clb, cw2, cb2,
                          ridx, cidx, gemb, gidx);
    proj_kernel<<<dim3(98, 9), 256>>>(x, Wq, bq, Wk, bk, Wv, bv);
    attn_kernel<<<392, 512, ATTN_SMEM_BYTES>>>();
    out_kernel<<<196, 512, OUT_SMEM_BYTES>>>(Wout, bout, out);
}

// round 5
// speedup vs baseline: 2.2130x; 1.0233x over previous
#include <cuda_runtime.h>
#include <math.h>

// Sizes: B=2, Cin=32, G=V=M=4, H=W=28, P=7, MID=48, HEADS=4, POS=16, Cout=64
// q/k/v layout: [(b*4+h)*4+g][yx][48c]
// g_pe: [v*49+kl][32c] (row 0..15, col 16..31)
// g_ge: [(v*4+g)*4+m][16c]
// g_o : [(b*4+v)*784+yx][192i]  with i = c*4+h

__device__ float g_q[1204224];
__device__ float g_k[1204224];
__device__ float g_v[1204224];
__device__ float g_pe[6272];
__device__ float g_ge[1024];
__device__ float g_o[1204224];

// ---------------------------------------------------------------------------
// PE MLP
// ---------------------------------------------------------------------------
__device__ __forceinline__ void pe_mlp(float tval,
    const float* __restrict__ w1, const float* __restrict__ b1,
    const float* __restrict__ lng, const float* __restrict__ lnb,
    const float* __restrict__ w2, const float* __restrict__ b2,
    float* outp)
{
    float hv[16];
    float mu = 0.f;
#pragma unroll
    for (int j = 0; j < 16; ++j) { hv[j] = tval * w1[j] + b1[j]; mu += hv[j]; }
    mu *= (1.f / 16.f);
    float var = 0.f;
#pragma unroll
    for (int j = 0; j < 16; ++j) { float d = hv[j] - mu; var += d * d; }
    var *= (1.f / 16.f);
    float rstd = rsqrtf(var + 1e-5f);
#pragma unroll
    for (int j = 0; j < 16; ++j) {
        float t = (hv[j] - mu) * rstd * lng[j] + lnb[j];
        hv[j] = t / (1.f + expf(-t));
    }
#pragma unroll
    for (int j = 0; j < 16; ++j) {
        float e = b2[j];
#pragma unroll
        for (int t = 0; t < 16; ++t) e += hv[t] * w2[j * 16 + t];
        outp[j] = e;
    }
}

__global__ void pe_kernel(
    const float* __restrict__ rw1, const float* __restrict__ rb1,
    const float* __restrict__ rlg, const float* __restrict__ rlb,
    const float* __restrict__ rw2, const float* __restrict__ rb2,
    const float* __restrict__ cw1, const float* __restrict__ cb1,
    const float* __restrict__ clg, const float* __restrict__ clb,
    const float* __restrict__ cw2, const float* __restrict__ cb2,
    const float* __restrict__ ridx, const float* __restrict__ cidx,
    const float* __restrict__ gemb, const int* __restrict__ gidx)
{
    int tid = threadIdx.x;
    if (tid < 196) {
        float er[16], ec[16];
        pe_mlp(ridx[tid], rw1, rb1, rlg, rlb, rw2, rb2, er);
        pe_mlp(cidx[tid], cw1, cb1, clg, clb, cw2, cb2, ec);
#pragma unroll
        for (int j = 0; j < 16; ++j) {
            g_pe[tid * 32 + j]      = er[j];
            g_pe[tid * 32 + 16 + j] = ec[j];
        }
    }
    for (int e = tid; e < 1024; e += blockDim.x) {
        int vgm = e >> 4, c = e & 15;
        g_ge[e] = gemb[gidx[vgm] * 16 + c];
    }
}

// ---------------------------------------------------------------------------
// proj: C[576 x 6272] = [Wq;Wk;Wv][576x32] * X[32x6272] -> g_q/k/v
// ---------------------------------------------------------------------------
__global__ void __launch_bounds__(256) proj_kernel(
    const float* __restrict__ x,
    const float* __restrict__ Wq, const float* __restrict__ bq,
    const float* __restrict__ Wk, const float* __restrict__ bk,
    const float* __restrict__ Wv, const float* __restrict__ bv)
{
    __shared__ float As[32 * 68];
    __shared__ float Bs[32 * 68];
    int tid = threadIdx.x;
    int n0 = blockIdx.x * 64;
    int r0 = blockIdx.y * 64;

#pragma unroll
    for (int k = 0; k < 8; ++k) {
        int i = tid + k * 256;
        int ci = i & 31, row = i >> 5;
        int rg = r0 + row;
        int which = rg / 192, r = rg - which * 192;
        const float* Wm = (which == 0) ? Wq : (which == 1 ? Wk : Wv);
        As[ci * 68 + row] = Wm[r * 32 + ci];
    }
#pragma unroll
    for (int k = 0; k < 8; ++k) {
        int i = tid + k * 256;
        int nl = i & 63, ci = i >> 6;
        int n = n0 + nl;
        int bb = n / 3136, rem = n - bb * 3136;
        Bs[ci * 68 + nl] = x[bb * 100352 + ci * 3136 + rem];
    }
    __syncthreads();

    int tx = tid & 15, ty = tid >> 4;
    float acc[4][4] = {};
#pragma unroll
    for (int ci = 0; ci < 32; ++ci) {
        float4 a4 = *(const float4*)&As[ci * 68 + ty * 4];
        float4 b4 = *(const float4*)&Bs[ci * 68 + tx * 4];
        float av[4] = { a4.x, a4.y, a4.z, a4.w };
        float bw[4] = { b4.x, b4.y, b4.z, b4.w };
#pragma unroll
        for (int u = 0; u < 4; ++u)
#pragma unroll
            for (int w = 0; w < 4; ++w) acc[u][w] += av[u] * bw[w];
    }

#pragma unroll
    for (int u = 0; u < 4; ++u) {
        int rg = r0 + ty * 4 + u;
        int which = rg / 192, r = rg - which * 192;
        int c = r >> 2, hh = r & 3;
        float bias = ((which == 0) ? bq : (which == 1 ? bk : bv))[r];
        float* dst = (which == 0) ? g_q : (which == 1 ? g_k : g_v);
#pragma unroll
        for (int w = 0; w < 4; ++w) {
            int n = n0 + tx * 4 + w;
            int bb = n / 3136, rem = n - bb * 3136;
            int gg = rem / 784, yx = rem - gg * 784;
            dst[(((bb * 4 + hh) * 4 + gg) * 784 + yx) * 48 + c] = acc[u][w] + bias;
        }
    }
}

// ---------------------------------------------------------------------------
// attn: one block per (b,h, 4x4 pixel tile). 512 threads = 16 warps = 1 site/warp.
// ---------------------------------------------------------------------------
#define SM_PE    0        // [196][36]  (float4-aligned rows)
#define SM_GE    7056     // [64][16]
#define SM_QS    8080     // [16 sites][4 g][48 c]
#define SM_SLAB  11152    // [48 c][401]  pos = m*100 + sy*10 + sx
#define SM_SCR   30400    // per-warp: rc 784 | w 784 | gs 64 = 1632
#define SCR_WARP 1632
#define ATTN_SMEM_FLOATS (SM_SCR + 16 * SCR_WARP)  // 56512
#define ATTN_SMEM_BYTES  (ATTN_SMEM_FLOATS * 4)    // 226048

// synchronous slab loader (k): thread = (c, sx), walk m,sy with constant offsets
__device__ __forceinline__ void load_slab(float* slab, const float* __restrict__ src,
                                          int bh, int ty0, int tx0, int tid)
{
    if (tid < 480) {
        int c  = tid % 48;
        int sx = tid / 48;                       // 0..9
        int xx = tx0 - 3 + sx;
        bool xok = (unsigned)xx < 28u;
        float* sdst = slab + c * 401 + sx;
        const float* gbase = src + (bh * 4) * 37632 + xx * 48 + c;
#pragma unroll
        for (int m = 0; m < 4; ++m) {
#pragma unroll
            for (int sy = 0; sy < 10; ++sy) {
                int y = ty0 - 3 + sy;
                float val = 0.f;
                if (xok && (unsigned)y < 28u)
                    val = gbase[m * 37632 + y * 1344];
                sdst[m * 100 + sy * 10] = val;
            }
        }
    }
}

// async slab loader (v): cp.async with src-size 0 => zero-fill for OOB
__device__ __forceinline__ void load_slab_async(float* slab, const float* __restrict__ src,
                                                int bh, int ty0, int tx0, int tid)
{
    if (tid < 480) {
        int c  = tid % 48;
        int sx = tid / 48;
        int xx = tx0 - 3 + sx;
        bool xok = (unsigned)xx < 28u;
        int xc = xok ? xx : 0;
        unsigned int sdst = (unsigned int)__cvta_generic_to_shared(slab + c * 401 + sx);
        const float* gbase = src + (bh * 4) * 37632 + xc * 48 + c;
#pragma unroll
        for (int m = 0; m < 4; ++m) {
#pragma unroll
            for (int sy = 0; sy < 10; ++sy) {
                int y = ty0 - 3 + sy;
                bool ok = xok && ((unsigned)y < 28u);
                int yc = ok ? y : 0;
                const float* gp = gbase + m * 37632 + yc * 1344;
                unsigned int sa = sdst + (unsigned int)((m * 100 + sy * 10) * 4);
                int sz = ok ? 4 : 0;
                asm volatile("cp.async.ca.shared.global [%0], [%1], 4, %2;\n"
                             :: "r"(sa), "l"(gp), "r"(sz));
            }
        }
    }
    asm volatile("cp.async.commit_group;\n" ::: "memory");
}

__global__ void __launch_bounds__(512, 1) attn_kernel()
{
    extern __shared__ float sm[];
    float* pes  = sm + SM_PE;
    float* ges  = sm + SM_GE;
    float* qs   = sm + SM_QS;
    float* slab = sm + SM_SLAB;

    const int tid  = threadIdx.x, lane = tid & 31, warp = tid >> 5;
    const int tile = blockIdx.x % 49;
    const int bh   = blockIdx.x / 49;
    const int b    = bh >> 2, h = bh & 3;
    const int ty0  = (tile / 7) * 4, tx0 = (tile % 7) * 4;

    for (int i = tid; i < 6272; i += 512) pes[(i >> 5) * 36 + (i & 31)] = g_pe[i];
    for (int i = tid; i < 1024; i += 512) ges[i] = g_ge[i];
    for (int i = tid; i < 3072; i += 512) {
        int site = i / 192, r = i - site * 192, gg = r / 48, c = r - gg * 48;
        int yx = (ty0 + (site >> 2)) * 28 + tx0 + (site & 3);
        qs[i] = g_q[((bh * 4 + gg) * 784 + yx) * 48 + c];
    }
    load_slab(slab, g_k, bh, ty0, tx0, tid);
    __syncthreads();

    float* scr  = sm + SM_SCR + warp * SCR_WARP;
    float* rc_s = scr;            // 784: [v][g][49 kl]
    float* w_s  = scr + 784;      // 784: [196 p][4 v]
    float* gs_s = scr + 1568;     // 64 : [v][g][4 m]

    const int site = warp;
    const int ly = site >> 2, lx = site & 3;
    const float* qsi = qs + site * 192;

    // =============== Phase 1: scores + softmax -> w[p][4v] =================
    // group scores gs[v][g][m]
#pragma unroll
    for (int u = 0; u < 2; ++u) {
        int e = lane * 2 + u;
        int gg = (e >> 2) & 3;
        float a = 0.f;
#pragma unroll
        for (int c = 0; c < 16; ++c)
            a += qsi[gg * 48 + 32 + c] * ges[e * 16 + c];
        gs_s[e] = a;
    }

    // per-lane entry mapping: p = lane + 32*t over 196 = 4m x 49kl
    int kl_t[7], m_t[7], pos_t[7];
    bool valid[7], act[7];
#pragma unroll
    for (int t = 0; t < 7; ++t) {
        int p = lane + 32 * t;
        act[t] = (p < 196);
        int pc = act[t] ? p : 0;
        int m = pc / 49, kl = pc - m * 49, kk = kl / 7, ll = kl - kk * 7;
        kl_t[t] = kl; m_t[t] = m;
        pos_t[t] = m * 100 + (ly + kk) * 10 + (lx + ll);
        int y = ty0 + ly + kk - 3, xx = tx0 + lx + ll - 3;
        valid[t] = act[t] && ((unsigned)y < 28u) && ((unsigned)xx < 28u);
    }

    // content[g][t] = sum_c q[g][c] * k_slab[c][pos_t]
    float acc[4][7];
#pragma unroll
    for (int gg = 0; gg < 4; ++gg)
#pragma unroll
        for (int t = 0; t < 7; ++t) acc[gg][t] = 0.f;
    {
        const float4* q4p = (const float4*)qsi;
        for (int c4 = 0; c4 < 12; ++c4) {
            float4 qa = q4p[c4], qb = q4p[12 + c4], qc = q4p[24 + c4], qd = q4p[36 + c4];
            float qr[4][4] = { { qa.x, qa.y, qa.z, qa.w },
                               { qb.x, qb.y, qb.z, qb.w },
                               { qc.x, qc.y, qc.z, qc.w },
                               { qd.x, qd.y, qd.z, qd.w } };
#pragma unroll
            for (int u = 0; u < 4; ++u) {
                const float* sr = slab + (c4 * 4 + u) * 401;
#pragma unroll
                for (int t = 0; t < 7; ++t) {
                    float sv = sr[pos_t[t]];
                    acc[0][t] += qr[0][u] * sv; acc[1][t] += qr[1][u] * sv;
                    acc[2][t] += qr[2][u] * sv; acc[3][t] += qr[3][u] * sv;
                }
            }
        }
    }

    // k-slab reads complete; start async v-slab refill (overlaps rc + softmax)
    __syncthreads();
    load_slab_async(slab, g_v, bh, ty0, tx0, tid);

    // rc[v][g][kl] = sum_{c<32} q[g][c]*pe[v][kl][c]
    // g-outer: q hoisted to regs (broadcast LDS); pe streamed float4 per lane.
#pragma unroll 1
    for (int gg = 0; gg < 4; ++gg) {
        float qreg[32];
        const float4* qg4 = (const float4*)(qsi + gg * 48);
#pragma unroll
        for (int j = 0; j < 8; ++j) {
            float4 tq = qg4[j];
            qreg[j * 4 + 0] = tq.x; qreg[j * 4 + 1] = tq.y;
            qreg[j * 4 + 2] = tq.z; qreg[j * 4 + 3] = tq.w;
        }
        for (int e = lane; e < 196; e += 32) {       // e = v*49 + kl
            const float4* per = (const float4*)(pes + e * 36);
            float a = 0.f;
#pragma unroll
            for (int c4 = 0; c4 < 8; ++c4) {
                float4 p4 = per[c4];
                a += p4.x * qreg[c4 * 4 + 0] + p4.y * qreg[c4 * 4 + 1]
                   + p4.z * qreg[c4 * 4 + 2] + p4.w * qreg[c4 * 4 + 3];
            }
            int v = e / 49, kl = e - v * 49;
            rc_s[(v * 4 + gg) * 49 + kl] = a;
        }
    }
    __syncwarp();

    // softmax over (m,kl) per (v,g); g-pairs interleaved for latency overlap
    const float inv_sqn = 0.17677669529663687f;   // 1/sqrt(32)
    for (int v = 0; v < 4; ++v) {
        float wacc[7];
#pragma unroll
        for (int t = 0; t < 7; ++t) wacc[t] = 0.f;
#pragma unroll 1
        for (int gp = 0; gp < 2; ++gp) {
            int g0 = gp * 2, g1 = gp * 2 + 1;
            int vg0 = v * 4 + g0, vg1 = v * 4 + g1;
            float s0[7], s1[7];
            float mx0 = -1e30f, mx1 = -1e30f;
#pragma unroll
            for (int t = 0; t < 7; ++t) {
                if (valid[t]) {
                    float base_r0 = rc_s[vg0 * 49 + kl_t[t]];
                    float base_r1 = rc_s[vg1 * 49 + kl_t[t]];
                    s0[t] = (acc[g0][t] + base_r0 + gs_s[vg0 * 4 + m_t[t]]) * inv_sqn;
                    s1[t] = (acc[g1][t] + base_r1 + gs_s[vg1 * 4 + m_t[t]]) * inv_sqn;
                    mx0 = fmaxf(mx0, s0[t]); mx1 = fmaxf(mx1, s1[t]);
                } else { s0[t] = -1e30f; s1[t] = -1e30f; }
            }
#pragma unroll
            for (int o = 16; o; o >>= 1) {
                mx0 = fmaxf(mx0, __shfl_xor_sync(0xffffffffu, mx0, o));
                mx1 = fmaxf(mx1, __shfl_xor_sync(0xffffffffu, mx1, o));
            }
            float sum0 = 0.f, sum1 = 0.f;
#pragma unroll
            for (int t = 0; t < 7; ++t) {
                s0[t] = __expf(s0[t] - mx0); sum0 += s0[t];
                s1[t] = __expf(s1[t] - mx1); sum1 += s1[t];
            }
#pragma unroll
            for (int o = 16; o; o >>= 1) {
                sum0 += __shfl_xor_sync(0xffffffffu, sum0, o);
                sum1 += __shfl_xor_sync(0xffffffffu, sum1, o);
            }
            float inv0 = 1.f / sum0, inv1 = 1.f / sum1;
#pragma unroll
            for (int t = 0; t < 7; ++t)
                wacc[t] += s0[t] * inv0 + s1[t] * inv1;
        }
#pragma unroll
        for (int t = 0; t < 7; ++t)
            if (act[t]) w_s[(lane + 32 * t) * 4 + v] = wacc[t];
    }

    // v-slab fully landed + all warps' w ready
    asm volatile("cp.async.wait_group 0;\n" ::: "memory");
    __syncthreads();

    // =============== Phase 2: combine o[c][v] = sum_p w[p][v]*vslab[c][pos] =
    {
        const float4* w4 = (const float4*)w_s;
        const int yx = (ty0 + ly) * 28 + tx0 + lx;

        // pass A: c = lane (0..31), full p range
        {
            int c = lane;
            float a0 = 0.f, a1 = 0.f, a2 = 0.f, a3 = 0.f;
            for (int m = 0; m < 4; ++m) {
#pragma unroll
                for (int kk = 0; kk < 7; ++kk) {
                    const float* srow = slab + c * 401 + m * 100 + (ly + kk) * 10 + lx;
                    int p = m * 49 + kk * 7;
#pragma unroll
                    for (int ll = 0; ll < 7; ++ll) {
                        float sv = srow[ll];
                        float4 wv = w4[p + ll];
                        a0 += wv.x * sv; a1 += wv.y * sv;
                        a2 += wv.z * sv; a3 += wv.w * sv;
                    }
                }
            }
            int ch = c * 4 + h;
            g_o[((b * 4 + 0) * 784 + yx) * 192 + ch] = a0;
            g_o[((b * 4 + 1) * 784 + yx) * 192 + ch] = a1;
            g_o[((b * 4 + 2) * 784 + yx) * 192 + ch] = a2;
            g_o[((b * 4 + 3) * 784 + yx) * 192 + ch] = a3;
        }

        // pass B: c = 32 + (lane&15); half-warps split m-range, merge via shfl
        {
            int c = 32 + (lane & 15);
            int half = lane >> 4;
            float a0 = 0.f, a1 = 0.f, a2 = 0.f, a3 = 0.f;
#pragma unroll
            for (int mm = 0; mm < 2; ++mm) {
                int m = half * 2 + mm;
#pragma unroll
                for (int kk = 0; kk < 7; ++kk) {
                    const float* srow = slab + c * 401 + m * 100 + (ly + kk) * 10 + lx;
                    int p = m * 49 + kk * 7;
#pragma unroll
                    for (int ll = 0; ll < 7; ++ll) {
                        float sv = srow[ll];
                        float4 wv = w4[p + ll];
                        a0 += wv.x * sv; a1 += wv.y * sv;
                        a2 += wv.z * sv; a3 += wv.w * sv;
                    }
                }
            }
            a0 += __shfl_xor_sync(0xffffffffu, a0, 16);
            a1 += __shfl_xor_sync(0xffffffffu, a1, 16);
            a2 += __shfl_xor_sync(0xffffffffu, a2, 16);
            a3 += __shfl_xor_sync(0xffffffffu, a3, 16);
            if (lane < 16) {
                int ch = c * 4 + h;
                g_o[((b * 4 + 0) * 784 + yx) * 192 + ch] = a0;
                g_o[((b * 4 + 1) * 784 + yx) * 192 + ch] = a1;
                g_o[((b * 4 + 2) * 784 + yx) * 192 + ch] = a2;
                g_o[((b * 4 + 3) * 784 + yx) * 192 + ch] = a3;
            }
        }
    }
}

// ---------------------------------------------------------------------------
// out: out[b][o][v][yx] = sum_i Wout[o][i]*g_o[site][i] + bout[o]
// 392 blocks x 256 threads, 65KB smem -> 3 CTAs/SM (0.88 waves).
// warp w covers o-groups {2w, 2w+1}; lanes 0-15 / 16-31 are the two halves.
// Ws[i*68+o4]: half-warp-uniform broadcast. Gs[i*17+site]: broadcast pairs.
// ---------------------------------------------------------------------------
#define OUT_SMEM_FLOATS (192 * 68 + 192 * 17)   // 16320
#define OUT_SMEM_BYTES  (OUT_SMEM_FLOATS * 4)   // 65280

__global__ void __launch_bounds__(256) out_kernel(
    const float* __restrict__ Wout, const float* __restrict__ bout,
    float* __restrict__ out)
{
    extern __shared__ float smo[];
    float* Ws = smo;                 // [192 i][68] (o in low dim)
    float* Gs = smo + 192 * 68;      // [192 i][17] (site in low dim)
    int tid = threadIdx.x;
    for (int idx = tid; idx < 12288; idx += 256) {
        int o = idx / 192, i = idx - o * 192;
        Ws[i * 68 + o] = Wout[idx];
    }
    const float4* gsrc = (const float4*)(g_o + blockIdx.x * 3072);
    for (int idx = tid; idx < 768; idx += 256) {
        float4 vv = gsrc[idx];
        int site = idx / 48, off = (idx - site * 48) * 4;
        Gs[(off + 0) * 17 + site] = vv.x;
        Gs[(off + 1) * 17 + site] = vv.y;
        Gs[(off + 2) * 17 + site] = vv.z;
        Gs[(off + 3) * 17 + site] = vv.w;
    }
    __syncthreads();

    int w  = tid >> 5;
    int og = 2 * w + ((tid >> 4) & 1);   // half-warp uniform
    int o4 = og * 4;
    int sl = tid & 15;
    float a0 = bout[o4], a1 = bout[o4 + 1], a2 = bout[o4 + 2], a3 = bout[o4 + 3];
#pragma unroll 8
    for (int i = 0; i < 192; ++i) {
        float gv = Gs[i * 17 + sl];
        float4 wv = *(const float4*)(Ws + i * 68 + o4);
        a0 += wv.x * gv; a1 += wv.y * gv; a2 += wv.z * gv; a3 += wv.w * gv;
    }
    int site = blockIdx.x * 16 + sl;
    int bb = site / 3136, rem = site - bb * 3136;
    float* op = out + bb * 200704 + rem;
    op[(o4 + 0) * 3136] = a0;
    op[(o4 + 1) * 3136] = a1;
    op[(o4 + 2) * 3136] = a2;
    op[(o4 + 3) * 3136] = a3;
}

// ---------------------------------------------------------------------------
extern "C" void kernel_launch(void* const* d_in, const int* in_sizes, int n_in,
                              void* d_out, int out_size)
{
    const float* x    = (const float*)d_in[0];
    const float* Wq   = (const float*)d_in[1];  const float* bq = (const float*)d_in[2];
    const float* Wk   = (const float*)d_in[3];  const float* bk = (const float*)d_in[4];
    const float* Wv   = (const float*)d_in[5];  const float* bv = (const float*)d_in[6];
    const float* Wout = (const float*)d_in[7];  const float* bout = (const float*)d_in[8];
    const float* rw1  = (const float*)d_in[9];  const float* rb1 = (const float*)d_in[10];
    const float* rlg  = (const float*)d_in[11]; const float* rlb = (const float*)d_in[12];
    const float* rw2  = (const float*)d_in[13]; const float* rb2 = (const float*)d_in[14];
    const float* cw1  = (const float*)d_in[15]; const float* cb1 = (const float*)d_in[16];
    const float* clg  = (const float*)d_in[17]; const float* clb = (const float*)d_in[18];
    const float* cw2  = (const float*)d_in[19]; const float* cb2 = (const float*)d_in[20];
    const float* gemb = (const float*)d_in[21];
    const float* ridx = (const float*)d_in[22];
    const float* cidx = (const float*)d_in[23];
    const int*   gidx = (const int*)d_in[24];
    float* out = (float*)d_out;

    cudaFuncSetAttribute((const void*)attn_kernel,
                         cudaFuncAttributeMaxDynamicSharedMemorySize, ATTN_SMEM_BYTES);
    cudaFuncSetAttribute((const void*)out_kernel,
                         cudaFuncAttributeMaxDynamicSharedMemorySize, OUT_SMEM_BYTES);

    pe_kernel<<<1, 256>>>(rw1, rb1, rlg, rlb, rw2, rb2,
                          cw1, cb1, clg, clb, cw2, cb2,
                          ridx, cidx, gemb, gidx);
    proj_kernel<<<dim3(98, 9), 256>>>(x, Wq, bq, Wk, bk, Wv, bv);
    attn_kernel<<<392, 512, ATTN_SMEM_BYTES>>>();
    out_kernel<<<392, 256, OUT_SMEM_BYTES>>>(Wout, bout, out);
}

// round 6
// speedup vs baseline: 2.2736x; 1.0274x over previous
#include <cuda_runtime.h>
#include <math.h>

// Sizes: B=2, Cin=32, G=V=M=4, H=W=28, P=7, MID=48, HEADS=4, POS=16, Cout=64
// q/k/v layout: [(b*4+h)*4+g][yx][48c]
// g_pe: [v*49+kl][32c] (row 0..15, col 16..31)
// g_ge: [(v*4+g)*4+m][16c]
// g_o : [(b*4+v)*784+yx][192i]  with i = c*4+h

__device__ float g_q[1204224];
__device__ float g_k[1204224];
__device__ float g_v[1204224];
__device__ float g_pe[6272];
__device__ float g_ge[1024];
__device__ float g_o[1204224];

// ---------------------------------------------------------------------------
// PE MLP
// ---------------------------------------------------------------------------
__device__ __forceinline__ void pe_mlp(float tval,
    const float* __restrict__ w1, const float* __restrict__ b1,
    const float* __restrict__ lng, const float* __restrict__ lnb,
    const float* __restrict__ w2, const float* __restrict__ b2,
    float* outp)
{
    float hv[16];
    float mu = 0.f;
#pragma unroll
    for (int j = 0; j < 16; ++j) { hv[j] = tval * w1[j] + b1[j]; mu += hv[j]; }
    mu *= (1.f / 16.f);
    float var = 0.f;
#pragma unroll
    for (int j = 0; j < 16; ++j) { float d = hv[j] - mu; var += d * d; }
    var *= (1.f / 16.f);
    float rstd = rsqrtf(var + 1e-5f);
#pragma unroll
    for (int j = 0; j < 16; ++j) {
        float t = (hv[j] - mu) * rstd * lng[j] + lnb[j];
        hv[j] = t / (1.f + expf(-t));
    }
#pragma unroll
    for (int j = 0; j < 16; ++j) {
        float e = b2[j];
#pragma unroll
        for (int t = 0; t < 16; ++t) e += hv[t] * w2[j * 16 + t];
        outp[j] = e;
    }
}

__global__ void pe_kernel(
    const float* __restrict__ rw1, const float* __restrict__ rb1,
    const float* __restrict__ rlg, const float* __restrict__ rlb,
    const float* __restrict__ rw2, const float* __restrict__ rb2,
    const float* __restrict__ cw1, const float* __restrict__ cb1,
    const float* __restrict__ clg, const float* __restrict__ clb,
    const float* __restrict__ cw2, const float* __restrict__ cb2,
    const float* __restrict__ ridx, const float* __restrict__ cidx,
    const float* __restrict__ gemb, const int* __restrict__ gidx)
{
    int tid = threadIdx.x;
    if (tid < 196) {
        float er[16], ec[16];
        pe_mlp(ridx[tid], rw1, rb1, rlg, rlb, rw2, rb2, er);
        pe_mlp(cidx[tid], cw1, cb1, clg, clb, cw2, cb2, ec);
#pragma unroll
        for (int j = 0; j < 16; ++j) {
            g_pe[tid * 32 + j]      = er[j];
            g_pe[tid * 32 + 16 + j] = ec[j];
        }
    }
    for (int e = tid; e < 1024; e += blockDim.x) {
        int vgm = e >> 4, c = e & 15;
        g_ge[e] = gemb[gidx[vgm] * 16 + c];
    }
}

// ---------------------------------------------------------------------------
// proj: C[576 x 6272] = [Wq;Wk;Wv][576x32] * X[32x6272] -> g_q/k/v
// ---------------------------------------------------------------------------
__global__ void __launch_bounds__(256) proj_kernel(
    const float* __restrict__ x,
    const float* __restrict__ Wq, const float* __restrict__ bq,
    const float* __restrict__ Wk, const float* __restrict__ bk,
    const float* __restrict__ Wv, const float* __restrict__ bv)
{
    __shared__ float As[32 * 68];
    __shared__ float Bs[32 * 68];
    int tid = threadIdx.x;
    int n0 = blockIdx.x * 64;
    int r0 = blockIdx.y * 64;

#pragma unroll
    for (int k = 0; k < 8; ++k) {
        int i = tid + k * 256;
        int ci = i & 31, row = i >> 5;
        int rg = r0 + row;
        int which = rg / 192, r = rg - which * 192;
        const float* Wm = (which == 0) ? Wq : (which == 1 ? Wk : Wv);
        As[ci * 68 + row] = Wm[r * 32 + ci];
    }
#pragma unroll
    for (int k = 0; k < 8; ++k) {
        int i = tid + k * 256;
        int nl = i & 63, ci = i >> 6;
        int n = n0 + nl;
        int bb = n / 3136, rem = n - bb * 3136;
        Bs[ci * 68 + nl] = x[bb * 100352 + ci * 3136 + rem];
    }
    __syncthreads();

    int tx = tid & 15, ty = tid >> 4;
    float acc[4][4] = {};
#pragma unroll
    for (int ci = 0; ci < 32; ++ci) {
        float4 a4 = *(const float4*)&As[ci * 68 + ty * 4];
        float4 b4 = *(const float4*)&Bs[ci * 68 + tx * 4];
        float av[4] = { a4.x, a4.y, a4.z, a4.w };
        float bw[4] = { b4.x, b4.y, b4.z, b4.w };
#pragma unroll
        for (int u = 0; u < 4; ++u)
#pragma unroll
            for (int w = 0; w < 4; ++w) acc[u][w] += av[u] * bw[w];
    }

#pragma unroll
    for (int u = 0; u < 4; ++u) {
        int rg = r0 + ty * 4 + u;
        int which = rg / 192, r = rg - which * 192;
        int c = r >> 2, hh = r & 3;
        float bias = ((which == 0) ? bq : (which == 1 ? bk : bv))[r];
        float* dst = (which == 0) ? g_q : (which == 1 ? g_k : g_v);
#pragma unroll
        for (int w = 0; w < 4; ++w) {
            int n = n0 + tx * 4 + w;
            int bb = n / 3136, rem = n - bb * 3136;
            int gg = rem / 784, yx = rem - gg * 784;
            dst[(((bb * 4 + hh) * 4 + gg) * 784 + yx) * 48 + c] = acc[u][w] + bias;
        }
    }
}

// ---------------------------------------------------------------------------
// attn: one block per (b,h, 4x4 pixel tile). 512 threads = 16 warps = 1 site/warp.
// ---------------------------------------------------------------------------
#define SM_PE    0        // [196][36]
#define SM_GE    7056     // [64][16]
#define SM_QS    8080     // [16 sites][196] (192 used, pad 4)
#define SM_SLAB  11216    // [48 c][401]  pos = m*100 + sy*10 + sx
#define SM_RC    30464    // [16 sites][788]  (v*4+g)*49 + kl
#define SM_SCR   43072    // per-warp: w 784 | gs 64 = 848
#define SCR_WARP 848
#define ATTN_SMEM_FLOATS (SM_SCR + 16 * SCR_WARP)  // 56640
#define ATTN_SMEM_BYTES  (ATTN_SMEM_FLOATS * 4)    // 226560

// synchronous slab loader (k): thread = (c, sx), walk m,sy with constant offsets
__device__ __forceinline__ void load_slab(float* slab, const float* __restrict__ src,
                                          int bh, int ty0, int tx0, int tid)
{
    if (tid < 480) {
        int c  = tid % 48;
        int sx = tid / 48;                       // 0..9
        int xx = tx0 - 3 + sx;
        bool xok = (unsigned)xx < 28u;
        float* sdst = slab + c * 401 + sx;
        const float* gbase = src + (bh * 4) * 37632 + xx * 48 + c;
#pragma unroll
        for (int m = 0; m < 4; ++m) {
#pragma unroll
            for (int sy = 0; sy < 10; ++sy) {
                int y = ty0 - 3 + sy;
                float val = 0.f;
                if (xok && (unsigned)y < 28u)
                    val = gbase[m * 37632 + y * 1344];
                sdst[m * 100 + sy * 10] = val;
            }
        }
    }
}

// async slab loader (v): cp.async with src-size 0 => zero-fill for OOB
__device__ __forceinline__ void load_slab_async(float* slab, const float* __restrict__ src,
                                                int bh, int ty0, int tx0, int tid)
{
    if (tid < 480) {
        int c  = tid % 48;
        int sx = tid / 48;
        int xx = tx0 - 3 + sx;
        bool xok = (unsigned)xx < 28u;
        int xc = xok ? xx : 0;
        unsigned int sdst = (unsigned int)__cvta_generic_to_shared(slab + c * 401 + sx);
        const float* gbase = src + (bh * 4) * 37632 + xc * 48 + c;
#pragma unroll
        for (int m = 0; m < 4; ++m) {
#pragma unroll
            for (int sy = 0; sy < 10; ++sy) {
                int y = ty0 - 3 + sy;
                bool ok = xok && ((unsigned)y < 28u);
                int yc = ok ? y : 0;
                const float* gp = gbase + m * 37632 + yc * 1344;
                unsigned int sa = sdst + (unsigned int)((m * 100 + sy * 10) * 4);
                int sz = ok ? 4 : 0;
                asm volatile("cp.async.ca.shared.global [%0], [%1], 4, %2;\n"
                             :: "r"(sa), "l"(gp), "r"(sz));
            }
        }
    }
    asm volatile("cp.async.commit_group;\n" ::: "memory");
}

__global__ void __launch_bounds__(512, 1) attn_kernel()
{
    extern __shared__ float sm[];
    float* pes  = sm + SM_PE;
    float* ges  = sm + SM_GE;
    float* qs   = sm + SM_QS;
    float* slab = sm + SM_SLAB;
    float* rc   = sm + SM_RC;

    const int tid  = threadIdx.x, lane = tid & 31, warp = tid >> 5;
    const int tile = blockIdx.x % 49;
    const int bh   = blockIdx.x / 49;
    const int b    = bh >> 2, h = bh & 3;
    const int ty0  = (tile / 7) * 4, tx0 = (tile % 7) * 4;

    for (int i = tid; i < 6272; i += 512) pes[(i >> 5) * 36 + (i & 31)] = g_pe[i];
    for (int i = tid; i < 1024; i += 512) ges[i] = g_ge[i];
    for (int i = tid; i < 3072; i += 512) {
        int site = i / 192, r = i - site * 192, gg = r / 48, c = r - gg * 48;
        int yx = (ty0 + (site >> 2)) * 28 + tx0 + (site & 3);
        qs[site * 196 + r] = g_q[((bh * 4 + gg) * 784 + yx) * 48 + c];
    }
    load_slab(slab, g_k, bh, ty0, tx0, tid);
    __syncthreads();

    float* scr  = sm + SM_SCR + warp * SCR_WARP;
    float* w_s  = scr;            // 784: [196 p][4 v]
    float* gs_s = scr + 784;      // 64 : [v][g][4 m]

    const int site = warp;
    const int ly = site >> 2, lx = site & 3;
    const float* qsi = qs + site * 196;

    // =============== Phase 1a: group scores gs[v][g][m] (per-warp) =========
#pragma unroll
    for (int u = 0; u < 2; ++u) {
        int e = lane * 2 + u;
        int gg = (e >> 2) & 3;
        float a = 0.f;
#pragma unroll
        for (int c = 0; c < 16; ++c)
            a += qsi[gg * 48 + 32 + c] * ges[e * 16 + c];
        gs_s[e] = a;
    }

    // per-lane entry mapping: p = lane + 32*t over 196 = 4m x 49kl
    int kl_t[7], m_t[7], pos_t[7];
    bool valid[7], act[7];
#pragma unroll
    for (int t = 0; t < 7; ++t) {
        int p = lane + 32 * t;
        act[t] = (p < 196);
        int pc = act[t] ? p : 0;
        int m = pc / 49, kl = pc - m * 49, kk = kl / 7, ll = kl - kk * 7;
        kl_t[t] = kl; m_t[t] = m;
        pos_t[t] = m * 100 + (ly + kk) * 10 + (lx + ll);
        int y = ty0 + ly + kk - 3, xx = tx0 + lx + ll - 3;
        valid[t] = act[t] && ((unsigned)y < 28u) && ((unsigned)xx < 28u);
    }

    // =============== Phase 1b: content[g][t] = sum_c q[g][c]*k[c][pos_t] ===
    float acc[4][7];
#pragma unroll
    for (int gg = 0; gg < 4; ++gg)
#pragma unroll
        for (int t = 0; t < 7; ++t) acc[gg][t] = 0.f;
    {
        const float4* q4p = (const float4*)qsi;
        for (int c4 = 0; c4 < 12; ++c4) {
            float4 qa = q4p[c4], qb = q4p[12 + c4], qc = q4p[24 + c4], qd = q4p[36 + c4];
            float qr[4][4] = { { qa.x, qa.y, qa.z, qa.w },
                               { qb.x, qb.y, qb.z, qb.w },
                               { qc.x, qc.y, qc.z, qc.w },
                               { qd.x, qd.y, qd.z, qd.w } };
#pragma unroll
            for (int u = 0; u < 4; ++u) {
                const float* sr = slab + (c4 * 4 + u) * 401;
#pragma unroll
                for (int t = 0; t < 7; ++t) {
                    float sv = sr[pos_t[t]];
                    acc[0][t] += qr[0][u] * sv; acc[1][t] += qr[1][u] * sv;
                    acc[2][t] += qr[2][u] * sv; acc[3][t] += qr[3][u] * sv;
                }
            }
        }
    }

    // k-slab reads complete; start async v-slab refill (overlaps rc + softmax)
    __syncthreads();
    load_slab_async(slab, g_v, bh, ty0, tx0, tid);

    // =============== Phase 1c: cooperative rc ===============================
    // rc[site][(v*4+g)*49+kl] = sum_{c<32} q[site][g][c]*pe[v*49+kl][c]
    // warps split the 196 (v,kl) columns; lane holds one (site,g) q-row in regs;
    // pe columns are warp-uniform LDS.128 (16B/op).
    {
        int colStart = warp * 12 + (warp < 4 ? warp : 4);
        int nCols = (warp < 4) ? 13 : 12;
#pragma unroll 1
        for (int pass = 0; pass < 2; ++pass) {
            int row = pass * 32 + lane;          // (site,g)
            int rsite = row >> 2, rg = row & 3;
            float qreg[32];
            const float4* q4 = (const float4*)(qs + rsite * 196 + rg * 48);
#pragma unroll
            for (int j = 0; j < 8; ++j) {
                float4 t4 = q4[j];
                qreg[j * 4 + 0] = t4.x; qreg[j * 4 + 1] = t4.y;
                qreg[j * 4 + 2] = t4.z; qreg[j * 4 + 3] = t4.w;
            }
            float* rcrow = rc + rsite * 788 + rg * 49;
            for (int cc = 0; cc < nCols; ++cc) {
                int e = colStart + cc;
                const float4* pe4 = (const float4*)(pes + e * 36);
                float a = 0.f;
#pragma unroll
                for (int j = 0; j < 8; ++j) {
                    float4 p4 = pe4[j];
                    a += p4.x * qreg[j * 4 + 0] + p4.y * qreg[j * 4 + 1]
                       + p4.z * qreg[j * 4 + 2] + p4.w * qreg[j * 4 + 3];
                }
                int v = e / 49, kl = e - v * 49;
                rcrow[v * 196 + kl] = a;         // (v*4+rg)*49+kl = v*196+rg*49+kl
            }
        }
    }
    __syncthreads();

    // =============== Phase 1d: softmax -> w[p][4v] ==========================
    const float* rc_site = rc + site * 788;
    const float inv_sqn = 0.17677669529663687f;   // 1/sqrt(32)
    for (int v = 0; v < 4; ++v) {
        float wacc[7];
#pragma unroll
        for (int t = 0; t < 7; ++t) wacc[t] = 0.f;
#pragma unroll 1
        for (int gp = 0; gp < 2; ++gp) {
            int g0 = gp * 2, g1 = gp * 2 + 1;
            int vg0 = v * 4 + g0, vg1 = v * 4 + g1;
            float s0[7], s1[7];
            float mx0 = -1e30f, mx1 = -1e30f;
#pragma unroll
            for (int t = 0; t < 7; ++t) {
                if (valid[t]) {
                    float base_r0 = rc_site[vg0 * 49 + kl_t[t]];
                    float base_r1 = rc_site[vg1 * 49 + kl_t[t]];
                    s0[t] = (acc[g0][t] + base_r0 + gs_s[vg0 * 4 + m_t[t]]) * inv_sqn;
                    s1[t] = (acc[g1][t] + base_r1 + gs_s[vg1 * 4 + m_t[t]]) * inv_sqn;
                    mx0 = fmaxf(mx0, s0[t]); mx1 = fmaxf(mx1, s1[t]);
                } else { s0[t] = -1e30f; s1[t] = -1e30f; }
            }
#pragma unroll
            for (int o = 16; o; o >>= 1) {
                mx0 = fmaxf(mx0, __shfl_xor_sync(0xffffffffu, mx0, o));
                mx1 = fmaxf(mx1, __shfl_xor_sync(0xffffffffu, mx1, o));
            }
            float sum0 = 0.f, sum1 = 0.f;
#pragma unroll
            for (int t = 0; t < 7; ++t) {
                s0[t] = __expf(s0[t] - mx0); sum0 += s0[t];
                s1[t] = __expf(s1[t] - mx1); sum1 += s1[t];
            }
#pragma unroll
            for (int o = 16; o; o >>= 1) {
                sum0 += __shfl_xor_sync(0xffffffffu, sum0, o);
                sum1 += __shfl_xor_sync(0xffffffffu, sum1, o);
            }
            float inv0 = 1.f / sum0, inv1 = 1.f / sum1;
#pragma unroll
            for (int t = 0; t < 7; ++t)
                wacc[t] += s0[t] * inv0 + s1[t] * inv1;
        }
#pragma unroll
        for (int t = 0; t < 7; ++t)
            if (act[t]) w_s[(lane + 32 * t) * 4 + v] = wacc[t];
    }

    // v-slab fully landed + all warps' w ready
    asm volatile("cp.async.wait_group 0;\n" ::: "memory");
    __syncthreads();

    // =============== Phase 2: combine o[c][v] = sum_p w[p][v]*vslab[c][pos] =
    {
        const float4* w4 = (const float4*)w_s;
        const int yx = (ty0 + ly) * 28 + tx0 + lx;

        // pass A: c = lane (0..31), full p range
        {
            int c = lane;
            float a0 = 0.f, a1 = 0.f, a2 = 0.f, a3 = 0.f;
            for (int m = 0; m < 4; ++m) {
#pragma unroll
                for (int kk = 0; kk < 7; ++kk) {
                    const float* srow = slab + c * 401 + m * 100 + (ly + kk) * 10 + lx;
                    int p = m * 49 + kk * 7;
#pragma unroll
                    for (int ll = 0; ll < 7; ++ll) {
                        float sv = srow[ll];
                        float4 wv = w4[p + ll];
                        a0 += wv.x * sv; a1 += wv.y * sv;
                        a2 += wv.z * sv; a3 += wv.w * sv;
                    }
                }
            }
            int ch = c * 4 + h;
            g_o[((b * 4 + 0) * 784 + yx) * 192 + ch] = a0;
            g_o[((b * 4 + 1) * 784 + yx) * 192 + ch] = a1;
            g_o[((b * 4 + 2) * 784 + yx) * 192 + ch] = a2;
            g_o[((b * 4 + 3) * 784 + yx) * 192 + ch] = a3;
        }

        // pass B: c = 32 + (lane&15); half-warps split m-range, merge via shfl
        {
            int c = 32 + (lane & 15);
            int half = lane >> 4;
            float a0 = 0.f, a1 = 0.f, a2 = 0.f, a3 = 0.f;
#pragma unroll
            for (int mm = 0; mm < 2; ++mm) {
                int m = half * 2 + mm;
#pragma unroll
                for (int kk = 0; kk < 7; ++kk) {
                    const float* srow = slab + c * 401 + m * 100 + (ly + kk) * 10 + lx;
                    int p = m * 49 + kk * 7;
#pragma unroll
                    for (int ll = 0; ll < 7; ++ll) {
                        float sv = srow[ll];
                        float4 wv = w4[p + ll];
                        a0 += wv.x * sv; a1 += wv.y * sv;
                        a2 += wv.z * sv; a3 += wv.w * sv;
                    }
                }
            }
            a0 += __shfl_xor_sync(0xffffffffu, a0, 16);
            a1 += __shfl_xor_sync(0xffffffffu, a1, 16);
            a2 += __shfl_xor_sync(0xffffffffu, a2, 16);
            a3 += __shfl_xor_sync(0xffffffffu, a3, 16);
            if (lane < 16) {
                int ch = c * 4 + h;
                g_o[((b * 4 + 0) * 784 + yx) * 192 + ch] = a0;
                g_o[((b * 4 + 1) * 784 + yx) * 192 + ch] = a1;
                g_o[((b * 4 + 2) * 784 + yx) * 192 + ch] = a2;
                g_o[((b * 4 + 3) * 784 + yx) * 192 + ch] = a3;
            }
        }
    }
}

// ---------------------------------------------------------------------------
// out: out[b][o][v][yx] = sum_i Wout[o][i]*g_o[site][i] + bout[o]
// 392 blocks x 256 threads, 65KB smem -> 3 CTAs/SM.
// Ws fill uses structured indexing (no div/mod); loop as in R5.
// ---------------------------------------------------------------------------
#define OUT_SMEM_FLOATS (192 * 68 + 192 * 17)   // 16320
#define OUT_SMEM_BYTES  (OUT_SMEM_FLOATS * 4)   // 65280

__global__ void __launch_bounds__(256) out_kernel(
    const float* __restrict__ Wout, const float* __restrict__ bout,
    float* __restrict__ out)
{
    extern __shared__ float smo[];
    float* Ws = smo;                 // [192 i][68] (o in low dim)
    float* Gs = smo + 192 * 68;      // [192 i][17] (site in low dim)
    int tid = threadIdx.x;

    // structured Ws fill: thread -> (o = tid>>2, i = (tid&3) + 4k)
    {
        int o = tid >> 2, i0 = tid & 3;
        const float* wsrc = Wout + o * 192;
#pragma unroll 4
        for (int k = 0; k < 48; ++k) {
            int i = i0 + k * 4;
            Ws[i * 68 + o] = wsrc[i];
        }
    }
    const float4* gsrc = (const float4*)(g_o + blockIdx.x * 3072);
    for (int idx = tid; idx < 768; idx += 256) {
        float4 vv = gsrc[idx];
        int site = idx / 48, off = (idx - site * 48) * 4;
        Gs[(off + 0) * 17 + site] = vv.x;
        Gs[(off + 1) * 17 + site] = vv.y;
        Gs[(off + 2) * 17 + site] = vv.z;
        Gs[(off + 3) * 17 + site] = vv.w;
    }
    __syncthreads();

    int w  = tid >> 5;
    int og = 2 * w + ((tid >> 4) & 1);   // half-warp uniform
    int o4 = og * 4;
    int sl = tid & 15;
    float a0 = bout[o4], a1 = bout[o4 + 1], a2 = bout[o4 + 2], a3 = bout[o4 + 3];
#pragma unroll 8
    for (int i = 0; i < 192; ++i) {
        float gv = Gs[i * 17 + sl];
        float4 wv = *(const float4*)(Ws + i * 68 + o4);
        a0 += wv.x * gv; a1 += wv.y * gv; a2 += wv.z * gv; a3 += wv.w * gv;
    }
    int site = blockIdx.x * 16 + sl;
    int bb = site / 3136, rem = site - bb * 3136;
    float* op = out + bb * 200704 + rem;
    op[(o4 + 0) * 3136] = a0;
    op[(o4 + 1) * 3136] = a1;
    op[(o4 + 2) * 3136] = a2;
    op[(o4 + 3) * 3136] = a3;
}

// ---------------------------------------------------------------------------
extern "C" void kernel_launch(void* const* d_in, const int* in_sizes, int n_in,
                              void* d_out, int out_size)
{
    const float* x    = (const float*)d_in[0];
    const float* Wq   = (const float*)d_in[1];  const float* bq = (const float*)d_in[2];
    const float* Wk   = (const float*)d_in[3];  const float* bk = (const float*)d_in[4];
    const float* Wv   = (const float*)d_in[5];  const float* bv = (const float*)d_in[6];
    const float* Wout = (const float*)d_in[7];  const float* bout = (const float*)d_in[8];
    const float* rw1  = (const float*)d_in[9];  const float* rb1 = (const float*)d_in[10];
    const float* rlg  = (const float*)d_in[11]; const float* rlb = (const float*)d_in[12];
    const float* rw2  = (const float*)d_in[13]; const float* rb2 = (const float*)d_in[14];
    const float* cw1  = (const float*)d_in[15]; const float* cb1 = (const float*)d_in[16];
    const float* clg  = (const float*)d_in[17]; const float* clb = (const float*)d_in[18];
    const float* cw2  = (const float*)d_in[19]; const float* cb2 = (const float*)d_in[20];
    const float* gemb = (const float*)d_in[21];
    const float* ridx = (const float*)d_in[22];
    const float* cidx = (const float*)d_in[23];
    const int*   gidx = (const int*)d_in[24];
    float* out = (float*)d_out;

    cudaFuncSetAttribute((const void*)attn_kernel,
                         cudaFuncAttributeMaxDynamicSharedMemorySize, ATTN_SMEM_BYTES);
    cudaFuncSetAttribute((const void*)out_kernel,
                         cudaFuncAttributeMaxDynamicSharedMemorySize, OUT_SMEM_BYTES);

    pe_kernel<<<1, 256>>>(rw1, rb1, rlg, rlb, rw2, rb2,
                          cw1, cb1, clg, clb, cw2, cb2,
                          ridx, cidx, gemb, gidx);
    proj_kernel<<<dim3(98, 9), 256>>>(x, Wq, bq, Wk, bk, Wv, bv);
    attn_kernel<<<392, 512, ATTN_SMEM_BYTES>>>();
    out_kernel<<<392, 256, OUT_SMEM_BYTES>>>(Wout, bout, out);
}